// round 11
// baseline (speedup 1.0000x reference)
#include <cuda_runtime.h>
#include <cuda_fp16.h>
#include <cstdint>
#include <math.h>

// ============================================================================
// ReasonNet via ldmatrix + mma.sync (HMMA), pure fp16 GEMMs (fp32 accum).
// Round 11: round-9 mainloop (4-stage, 128x256, 64x64 warp) + all-fragments
// preload per kt (no mid-iteration LDSM stall) + prefetch issued pre-compute.
// B=16, T=1024, C=1024, K=8, H=1536.  M = B*T = 16384.
// ============================================================================

#define MDIM 16384
#define CDIM 1024
#define HDIM 1536
#define KNEI 8
#define TSEQ 1024
#define QKVLD 3072

#define BK 32
#define KSTRIDE 40                  // halfs per smem row (80B: aligned + LDSM conflict-free)
#define ROWB 80
#define BM 128
#define BN 256
#define STG_A 0
#define STG_B 10240                 // 128*80
#define STG_BYTES 30720             // + 256*80
#define NSTG 4
#define MM_SMEM (NSTG * STG_BYTES)  // 122880 bytes (1 CTA/SM)

// ---------------------------------------------------------------------------
// Scratch (static device globals; runtime allocation forbidden).
// ---------------------------------------------------------------------------
__device__ __half g_qkv [(size_t)MDIM * QKVLD];   // fused q|k|v per hop (fp16)
__device__ __half g_ctx [(size_t)MDIM * CDIM];
__device__ __half g_h1  [(size_t)MDIM * CDIM];    // Wo output (both hops)
__device__ float  g_y   [(size_t)MDIM * CDIM];
__device__ __half g_yh  [(size_t)MDIM * CDIM];
__device__ __half g_f16 [(size_t)MDIM * CDIM];
__device__ __half g_xh  [(size_t)MDIM * CDIM];
__device__ __half g_hid [(size_t)MDIM * HDIM];
// Transposed fp16 weights: Wt[N][K].  QKV stacked (3072 rows).
__device__ __half g_wqkvh[(size_t)QKVLD * CDIM];
__device__ __half g_woh[(size_t)CDIM * CDIM];
__device__ __half g_w1h[(size_t)HDIM * CDIM];
__device__ __half g_w2h[(size_t)CDIM * HDIM];

// ---------------------------------------------------------------------------
// PTX helpers (sm_80-portable only)
// ---------------------------------------------------------------------------
__device__ __forceinline__ uint32_t smem_u32(const void* p) {
    uint32_t a;
    asm("{ .reg .u64 t; cvta.to.shared.u64 t, %1; cvt.u32.u64 %0, t; }"
        : "=r"(a) : "l"(p));
    return a;
}
__device__ __forceinline__ void cp16(uint32_t s, const void* g) {
    asm volatile("cp.async.cg.shared.global [%0], [%1], 16;" :: "r"(s), "l"(g) : "memory");
}
__device__ __forceinline__ void ldsm4(uint32_t* r, uint32_t addr) {
    asm volatile("ldmatrix.sync.aligned.m8n8.x4.shared.b16 {%0,%1,%2,%3}, [%4];"
                 : "=r"(r[0]), "=r"(r[1]), "=r"(r[2]), "=r"(r[3]) : "r"(addr));
}
__device__ __forceinline__ void mma16816(float* c, const uint32_t* a, const uint32_t* b) {
    asm volatile(
        "mma.sync.aligned.m16n8k16.row.col.f32.f16.f16.f32 "
        "{%0,%1,%2,%3}, {%4,%5,%6,%7}, {%8,%9}, {%0,%1,%2,%3};"
        : "+f"(c[0]), "+f"(c[1]), "+f"(c[2]), "+f"(c[3])
        : "r"(a[0]), "r"(a[1]), "r"(a[2]), "r"(a[3]), "r"(b[0]), "r"(b[1]));
}
// dot of 8 fp16 pairs (as uint4) accumulated in fp32
__device__ __forceinline__ float dot8(uint4 a, uint4 c) {
    const __half2* pa = (const __half2*)&a;
    const __half2* pc = (const __half2*)&c;
    float s = 0.f;
#pragma unroll
    for (int i = 0; i < 4; i++) {
        float2 fa = __half22float2(pa[i]);
        float2 fc = __half22float2(pc[i]);
        s += fa.x * fc.x + fa.y * fc.y;
    }
    return s;
}

// ---------------------------------------------------------------------------
// fp16 GEMM: C[M,N] = A[M,K] @ B[N,K]^T  (fp32 accumulate)
// flags: bit0 relu, bit1 write fp16 (Ch), bit2 write fp32 (Cf).
// 256 threads, 128x256 CTA tile, 64x64 warp tile, BK=32, 4-stage pipeline.
// Per kt: prefetch issue first, then ALL 16 ldsm4, then 64 MMAs.
// ---------------------------------------------------------------------------
__global__ __launch_bounds__(256, 1)
void mm_fp16_kernel(const __half* __restrict__ A, const __half* __restrict__ B,
                    float* __restrict__ Cf, __half* __restrict__ Ch,
                    const float* __restrict__ bias, int N, int K, int flags)
{
    extern __shared__ char smem[];
    const uint32_t sb = smem_u32(smem);
    const int tid  = threadIdx.x;
    const int wid  = tid >> 5;
    const int lane = tid & 31;
    const int bm   = blockIdx.y * BM;
    const int bn   = blockIdx.x * BN;
    const int wm   = (wid >> 2) * 64;   // 2 warps in M
    const int wn   = (wid & 3) * 64;    // 4 warps in N
    const int ntiles = K / BK;

    // -------- producer addressing --------
    const int rowA = tid & 127;
    const int sgA  = tid >> 7;          // 0/1; covers segs sgA, sgA+2
    const __half* gA = A + (size_t)(bm + rowA) * K;
    const __half* gB = B + (size_t)(bn + tid) * K;   // 256 B-rows, 1 per thread
    const uint32_t doffA = (uint32_t)rowA * ROWB;
    const uint32_t doffB = (uint32_t)tid * ROWB;

    auto issue = [&](int kt, int s) {
        const uint32_t st = sb + (uint32_t)s * STG_BYTES;
        const size_t kof = (size_t)kt * BK;
#pragma unroll
        for (int qq = 0; qq < 2; qq++) {
            const int seg = sgA + qq * 2;
            cp16(st + STG_A + doffA + seg * 16, gA + kof + seg * 8);
        }
#pragma unroll
        for (int seg = 0; seg < 4; seg++)
            cp16(st + STG_B + doffB + seg * 16, gB + kof + seg * 8);
        asm volatile("cp.async.commit_group;" ::: "memory");
    };

    float acc[4][8][4];
#pragma unroll
    for (int i = 0; i < 4; i++)
#pragma unroll
        for (int j = 0; j < 8; j++)
#pragma unroll
            for (int l = 0; l < 4; l++) acc[i][j][l] = 0.f;

    issue(0, 0);
    issue(1, 1);
    issue(2, 2);

    // ldmatrix lane addressing
    const int arow  = lane & 15;
    const int acol8 = (lane >> 4) * 8;
    const int brow  = (lane & 7) + ((lane >> 4) << 3);
    const int bcol8 = ((lane >> 3) & 1) * 8;

    for (int kt = 0; kt < ntiles; kt++) {
        if (kt < ntiles - 2)
            asm volatile("cp.async.wait_group 2;" ::: "memory");
        else if (kt == ntiles - 2)
            asm volatile("cp.async.wait_group 1;" ::: "memory");
        else
            asm volatile("cp.async.wait_group 0;" ::: "memory");
        __syncthreads();

        // prefetch BEFORE compute (overwrites stage (kt-1)%4, protected by barrier)
        if (kt + 3 < ntiles) issue(kt + 3, (kt + 3) % NSTG);

        const uint32_t stg = sb + (uint32_t)(kt % NSTG) * STG_BYTES;

        // ---- load ALL fragments for both ks halves up front ----
        uint32_t af[2][4][4], bf[2][4][4];
#pragma unroll
        for (int ks = 0; ks < 2; ks++) {
            const int kb = ks * 16;
#pragma unroll
            for (int mt = 0; mt < 4; mt++) {
                const uint32_t off =
                    (uint32_t)((wm + mt * 16 + arow) * KSTRIDE + kb + acol8) * 2;
                ldsm4(af[ks][mt], stg + STG_A + off);
            }
#pragma unroll
            for (int nt2 = 0; nt2 < 4; nt2++) {
                const uint32_t off =
                    (uint32_t)((wn + nt2 * 16 + brow) * KSTRIDE + kb + bcol8) * 2;
                ldsm4(bf[ks][nt2], stg + STG_B + off);
            }
        }

        // ---- 64 MMAs ----
#pragma unroll
        for (int ks = 0; ks < 2; ks++)
#pragma unroll
            for (int mt = 0; mt < 4; mt++)
#pragma unroll
                for (int nt = 0; nt < 8; nt++)
                    mma16816(acc[mt][nt], af[ks][mt], &bf[ks][nt >> 1][(nt & 1) * 2]);
    }

    // -------- epilogue --------
    const int g = lane >> 2;
    const int t = lane & 3;
#pragma unroll
    for (int mt = 0; mt < 4; mt++)
#pragma unroll
        for (int nt = 0; nt < 8; nt++) {
            const int gcol = bn + wn + nt * 8 + t * 2;
            float b0 = 0.f, b1 = 0.f;
            if (bias) { b0 = __ldg(&bias[gcol]); b1 = __ldg(&bias[gcol + 1]); }
#pragma unroll
            for (int half_ = 0; half_ < 2; half_++) {
                const int grow = bm + wm + mt * 16 + g + half_ * 8;
                float v0 = acc[mt][nt][half_ * 2 + 0] + b0;
                float v1 = acc[mt][nt][half_ * 2 + 1] + b1;
                if (flags & 1) { v0 = fmaxf(v0, 0.f); v1 = fmaxf(v1, 0.f); }
                const size_t o = (size_t)grow * N + gcol;
                if (flags & 4)
                    *(float2*)(Cf + o) = make_float2(v0, v1);
                if (flags & 2)
                    *(__half2*)(Ch + o) =
                        __halves2half2(__float2half_rn(v0), __float2half_rn(v1));
            }
        }
}

// ---------------------------------------------------------------------------
// ALL weight transposes in ONE launch.  blockIdx.z selects the matrix.
// ---------------------------------------------------------------------------
__global__ void thalf_all_kernel(const float* __restrict__ Wq, const float* __restrict__ Wk,
                                 const float* __restrict__ Wv, const float* __restrict__ Wo,
                                 const float* __restrict__ W1, const float* __restrict__ W2,
                                 __half* __restrict__ wqkv, __half* __restrict__ wo,
                                 __half* __restrict__ w1, __half* __restrict__ w2)
{
    const float* W;
    __half* T;
    int Kd, Nd;
    switch (blockIdx.z) {
        case 0: W = Wq; T = wqkv;                           Kd = CDIM; Nd = CDIM; break;
        case 1: W = Wk; T = wqkv + (size_t)CDIM * CDIM;     Kd = CDIM; Nd = CDIM; break;
        case 2: W = Wv; T = wqkv + (size_t)2 * CDIM * CDIM; Kd = CDIM; Nd = CDIM; break;
        case 3: W = Wo; T = wo;                             Kd = CDIM; Nd = CDIM; break;
        case 4: W = W1; T = w1;                             Kd = CDIM; Nd = HDIM; break;
        default: W = W2; T = w2;                            Kd = HDIM; Nd = CDIM; break;
    }
    const int bx = blockIdx.x * 32;
    const int by = blockIdx.y * 32;
    if (bx >= Nd || by >= Kd) return;

    __shared__ float t[32][33];
    const int x = threadIdx.x, y0 = threadIdx.y;
#pragma unroll
    for (int dy = 0; dy < 32; dy += 8)
        t[y0 + dy][x] = W[(size_t)(by + y0 + dy) * Nd + bx + x];
    __syncthreads();
#pragma unroll
    for (int dy = 0; dy < 32; dy += 8)
        T[(size_t)(bx + y0 + dy) * Kd + by + x] = __float2half_rn(t[x][y0 + dy]);
}

// Elementwise fp32 -> fp16 (for x).
__global__ void tohalf_kernel(const float* __restrict__ in, __half* __restrict__ o,
                              int n4)
{
    int i = blockIdx.x * blockDim.x + threadIdx.x;
    if (i >= n4) return;
    float4 a = ((const float4*)in)[i];
    ((__half2*)o)[i * 2]     = __halves2half2(__float2half_rn(a.x), __float2half_rn(a.y));
    ((__half2*)o)[i * 2 + 1] = __halves2half2(__float2half_rn(a.z), __float2half_rn(a.w));
}

// ---------------------------------------------------------------------------
// Neighbor attention (K=8); fp16 qkv[M][3072] = q|k|v, fp32 math, fp16 ctx out.
// ---------------------------------------------------------------------------
__global__ __launch_bounds__(256)
void attn_kernel(const __half* __restrict__ qkv, const float* __restrict__ radj,
                 const int* __restrict__ inxs, __half* __restrict__ ctx)
{
    const int bt = blockIdx.x;
    const int b = bt >> 10;
    const int tid = threadIdx.x;
    const int wid = tid >> 5, lid = tid & 31;

    __shared__ float s_scores[KNEI];
    __shared__ int s_rows[KNEI];
    if (tid < KNEI) s_rows[tid] = b * TSEQ + inxs[(size_t)bt * KNEI + tid];
    __syncthreads();

    const uint4* qv = (const uint4*)(qkv + (size_t)bt * QKVLD);
    const uint4* kv = (const uint4*)(qkv + (size_t)s_rows[wid] * QKVLD + CDIM);
    float sum = 0.f;
#pragma unroll
    for (int e = lid; e < CDIM / 8; e += 32)
        sum += dot8(qv[e], kv[e]);
#pragma unroll
    for (int o = 16; o > 0; o >>= 1) sum += __shfl_xor_sync(0xffffffffu, sum, o);
    if (lid == 0)
        s_scores[wid] = sum * 0.03125f + radj[(size_t)bt * KNEI + wid];
    __syncthreads();

    float w[KNEI];
    float mx = s_scores[0];
#pragma unroll
    for (int j = 1; j < KNEI; j++) mx = fmaxf(mx, s_scores[j]);
    float den = 0.f;
#pragma unroll
    for (int j = 0; j < KNEI; j++) { w[j] = expf(s_scores[j] - mx); den += w[j]; }
    const float inv = 1.f / den;

    float a0 = 0.f, a1 = 0.f, a2 = 0.f, a3 = 0.f;
#pragma unroll
    for (int j = 0; j < KNEI; j++) {
        const uint2 vv =
            ((const uint2*)(qkv + (size_t)s_rows[j] * QKVLD + 2 * CDIM))[tid];
        const __half2* pv = (const __half2*)&vv;
        const float2 f0 = __half22float2(pv[0]);
        const float2 f1 = __half22float2(pv[1]);
        const float wj = w[j] * inv;
        a0 = fmaf(wj, f0.x, a0); a1 = fmaf(wj, f0.y, a1);
        a2 = fmaf(wj, f1.x, a2); a3 = fmaf(wj, f1.y, a3);
    }
    uint2 ov;
    ((__half2*)&ov)[0] = __halves2half2(__float2half_rn(a0), __float2half_rn(a1));
    ((__half2*)&ov)[1] = __halves2half2(__float2half_rn(a2), __float2half_rn(a3));
    ((uint2*)(ctx + (size_t)bt * CDIM))[tid] = ov;
}

// ---------------------------------------------------------------------------
// Fused residual (+optional relu) LayerNorm.  Residual branch hb is fp16.
// ---------------------------------------------------------------------------
__global__ __launch_bounds__(256)
void ln_kernel(const float* __restrict__ a, const __half* __restrict__ hb,
               const float* __restrict__ g, const float* __restrict__ beta,
               float* __restrict__ out, __half* __restrict__ oh, int relu_h)
{
    __shared__ float sh1[8], sh2[8];
    const int bt = blockIdx.x;
    const int tid = threadIdx.x;
    const int wid = tid >> 5, lid = tid & 31;
    const size_t base = (size_t)bt * CDIM;

    float4 z = ((const float4*)(a + base))[tid];
    const uint2 hv = ((const uint2*)(hb + base))[tid];
    const __half2* ph = (const __half2*)&hv;
    const float2 h01 = __half22float2(ph[0]);
    const float2 h23 = __half22float2(ph[1]);
    float hx = h01.x, hy = h01.y, hz = h23.x, hw = h23.y;
    if (relu_h) {
        hx = fmaxf(hx, 0.f); hy = fmaxf(hy, 0.f);
        hz = fmaxf(hz, 0.f); hw = fmaxf(hw, 0.f);
    }
    z.x += hx; z.y += hy; z.z += hz; z.w += hw;

    float s = z.x + z.y + z.z + z.w;
    float ss = z.x * z.x + z.y * z.y + z.z * z.z + z.w * z.w;
#pragma unroll
    for (int o = 16; o > 0; o >>= 1) {
        s += __shfl_xor_sync(0xffffffffu, s, o);
        ss += __shfl_xor_sync(0xffffffffu, ss, o);
    }
    if (lid == 0) { sh1[wid] = s; sh2[wid] = ss; }
    __syncthreads();
    float ts = 0.f, tss = 0.f;
#pragma unroll
    for (int j = 0; j < 8; j++) { ts += sh1[j]; tss += sh2[j]; }

    const float mean = ts * (1.f / CDIM);
    const float var = tss * (1.f / CDIM) - mean * mean;
    const float rstd = rsqrtf(var + 1e-5f);

    const float4 gg = ((const float4*)g)[tid];
    const float4 bb = ((const float4*)beta)[tid];
    float4 o4;
    o4.x = (z.x - mean) * rstd * gg.x + bb.x;
    o4.y = (z.y - mean) * rstd * gg.y + bb.y;
    o4.z = (z.z - mean) * rstd * gg.z + bb.z;
    o4.w = (z.w - mean) * rstd * gg.w + bb.w;
    ((float4*)(out + base))[tid] = o4;
    if (oh) {
        const size_t b2 = (size_t)bt * (CDIM / 2) + tid * 2;
        ((__half2*)oh)[b2] =
            __halves2half2(__float2half_rn(o4.x), __float2half_rn(o4.y));
        ((__half2*)oh)[b2 + 1] =
            __halves2half2(__float2half_rn(o4.z), __float2half_rn(o4.w));
    }
}

// ---------------------------------------------------------------------------
// Launch
// ---------------------------------------------------------------------------
extern "C" void kernel_launch(void* const* d_in, const int* in_sizes, int n_in,
                              void* d_out, int out_size)
{
    const float* x    = (const float*)d_in[0];
    const float* radj = (const float*)d_in[1];
    const int*   inxs = (const int*)  d_in[2];
    const float* Wq   = (const float*)d_in[3];
    const float* Wk   = (const float*)d_in[4];
    const float* Wv   = (const float*)d_in[5];
    const float* Wo   = (const float*)d_in[6];
    const float* ln1g = (const float*)d_in[7];
    const float* ln1b = (const float*)d_in[8];
    const float* W1   = (const float*)d_in[9];
    const float* b1   = (const float*)d_in[10];
    const float* W2   = (const float*)d_in[11];
    const float* b2   = (const float*)d_in[12];
    const float* ln2g = (const float*)d_in[13];
    const float* ln2b = (const float*)d_in[14];
    float* out = (float*)d_out;

    float *y;
    __half *qkv, *ctx, *h1, *yh, *f16, *xh, *hid, *wqkvh, *woh, *w1h, *w2h;
    cudaGetSymbolAddress((void**)&qkv, g_qkv);
    cudaGetSymbolAddress((void**)&ctx, g_ctx);
    cudaGetSymbolAddress((void**)&h1, g_h1);
    cudaGetSymbolAddress((void**)&y, g_y);
    cudaGetSymbolAddress((void**)&yh, g_yh);
    cudaGetSymbolAddress((void**)&f16, g_f16);
    cudaGetSymbolAddress((void**)&xh, g_xh);
    cudaGetSymbolAddress((void**)&hid, g_hid);
    cudaGetSymbolAddress((void**)&wqkvh, g_wqkvh);
    cudaGetSymbolAddress((void**)&woh, g_woh);
    cudaGetSymbolAddress((void**)&w1h, g_w1h);
    cudaGetSymbolAddress((void**)&w2h, g_w2h);

    cudaFuncSetAttribute(mm_fp16_kernel,
                         cudaFuncAttributeMaxDynamicSharedMemorySize, MM_SMEM);

    const dim3 b256(256);

    thalf_all_kernel<<<dim3(HDIM / 32, HDIM / 32, 6), dim3(32, 8)>>>(
        Wq, Wk, Wv, Wo, W1, W2, wqkvh, woh, w1h, w2h);
    tohalf_kernel<<<(MDIM * CDIM / 4 + 255) / 256, b256>>>(x, xh, MDIM * CDIM / 4);

    const dim3 gQKV(QKVLD / BN, MDIM / BM);  // (12, 128)
    const dim3 gCC(CDIM / BN, MDIM / BM);    // (4, 128)
    const dim3 gCH(HDIM / BN, MDIM / BM);    // (6, 128)

    const __half* a16 = xh;
    for (int hop = 0; hop < 2; hop++) {
        mm_fp16_kernel<<<gQKV, 256, MM_SMEM>>>(a16, wqkvh, nullptr, qkv,
                                               nullptr, QKVLD, CDIM, 2);
        attn_kernel<<<MDIM, b256>>>(qkv, radj, inxs, ctx);
        mm_fp16_kernel<<<gCC, 256, MM_SMEM>>>(ctx, woh, nullptr, h1,
                                              nullptr, CDIM, CDIM, 2);
        a16 = h1;
    }

    // y = LN(x + relu(h));  + fp16 copy for FFN input
    ln_kernel<<<MDIM, b256>>>(x, h1, ln1g, ln1b, y, yh, 1);
    // hid = relu(y @ W1 + b1)  -> fp16
    mm_fp16_kernel<<<gCH, 256, MM_SMEM>>>(yh, w1h, nullptr, hid, b1, HDIM, CDIM, 1 | 2);
    // f = hid @ W2 + b2  -> fp16
    mm_fp16_kernel<<<gCC, 256, MM_SMEM>>>(hid, w2h, nullptr, f16, b2, CDIM, HDIM, 2);
    // out = LN(y + f)
    ln_kernel<<<MDIM, b256>>>(y, f16, ln2g, ln2b, out, nullptr, 0);
}

// round 12
// speedup vs baseline: 1.1443x; 1.1443x over previous
#include <cuda_runtime.h>
#include <cuda_fp16.h>
#include <cstdint>
#include <math.h>

// ============================================================================
// ReasonNet via ldmatrix + mma.sync (HMMA), pure fp16 GEMMs (fp32 accum).
// Round 12: exact round-9 GEMM mainloop (best known: 1954us) + fp16-only `y`
// (ln1 out fp16, ln2 residual-in fp16) to cut 134MB of fp32 traffic.
// B=16, T=1024, C=1024, K=8, H=1536.  M = B*T = 16384.
// ============================================================================

#define MDIM 16384
#define CDIM 1024
#define HDIM 1536
#define KNEI 8
#define TSEQ 1024
#define QKVLD 3072

#define BK 32
#define KSTRIDE 40                  // halfs per smem row (80B: aligned + LDSM conflict-free)
#define ROWB 80
#define BM 128
#define BN 256
#define STG_A 0
#define STG_B 10240                 // 128*80
#define STG_BYTES 30720             // + 256*80
#define NSTG 4
#define MM_SMEM (NSTG * STG_BYTES)  // 122880 bytes (1 CTA/SM)

// ---------------------------------------------------------------------------
// Scratch (static device globals; runtime allocation forbidden).
// ---------------------------------------------------------------------------
__device__ __half g_qkv [(size_t)MDIM * QKVLD];   // fused q|k|v per hop (fp16)
__device__ __half g_ctx [(size_t)MDIM * CDIM];
__device__ __half g_h1  [(size_t)MDIM * CDIM];    // Wo output (both hops)
__device__ __half g_yh  [(size_t)MDIM * CDIM];    // ln1 output (fp16 only)
__device__ __half g_f16 [(size_t)MDIM * CDIM];
__device__ __half g_xh  [(size_t)MDIM * CDIM];
__device__ __half g_hid [(size_t)MDIM * HDIM];
// Transposed fp16 weights: Wt[N][K].  QKV stacked (3072 rows).
__device__ __half g_wqkvh[(size_t)QKVLD * CDIM];
__device__ __half g_woh[(size_t)CDIM * CDIM];
__device__ __half g_w1h[(size_t)HDIM * CDIM];
__device__ __half g_w2h[(size_t)CDIM * HDIM];

// ---------------------------------------------------------------------------
// PTX helpers (sm_80-portable only)
// ---------------------------------------------------------------------------
__device__ __forceinline__ uint32_t smem_u32(const void* p) {
    uint32_t a;
    asm("{ .reg .u64 t; cvta.to.shared.u64 t, %1; cvt.u32.u64 %0, t; }"
        : "=r"(a) : "l"(p));
    return a;
}
__device__ __forceinline__ void cp16(uint32_t s, const void* g) {
    asm volatile("cp.async.cg.shared.global [%0], [%1], 16;" :: "r"(s), "l"(g) : "memory");
}
__device__ __forceinline__ void ldsm4(uint32_t* r, uint32_t addr) {
    asm volatile("ldmatrix.sync.aligned.m8n8.x4.shared.b16 {%0,%1,%2,%3}, [%4];"
                 : "=r"(r[0]), "=r"(r[1]), "=r"(r[2]), "=r"(r[3]) : "r"(addr));
}
__device__ __forceinline__ void mma16816(float* c, const uint32_t* a, const uint32_t* b) {
    asm volatile(
        "mma.sync.aligned.m16n8k16.row.col.f32.f16.f16.f32 "
        "{%0,%1,%2,%3}, {%4,%5,%6,%7}, {%8,%9}, {%0,%1,%2,%3};"
        : "+f"(c[0]), "+f"(c[1]), "+f"(c[2]), "+f"(c[3])
        : "r"(a[0]), "r"(a[1]), "r"(a[2]), "r"(a[3]), "r"(b[0]), "r"(b[1]));
}
// dot of 8 fp16 pairs (as uint4) accumulated in fp32
__device__ __forceinline__ float dot8(uint4 a, uint4 c) {
    const __half2* pa = (const __half2*)&a;
    const __half2* pc = (const __half2*)&c;
    float s = 0.f;
#pragma unroll
    for (int i = 0; i < 4; i++) {
        float2 fa = __half22float2(pa[i]);
        float2 fc = __half22float2(pc[i]);
        s += fa.x * fc.x + fa.y * fc.y;
    }
    return s;
}

// ---------------------------------------------------------------------------
// fp16 GEMM: C[M,N] = A[M,K] @ B[N,K]^T  (fp32 accumulate)
// flags: bit0 relu, bit1 write fp16 (Ch), bit2 write fp32 (Cf).
// 256 threads, 128x256 CTA tile, 64x64 warp tile, BK=32, 4-stage pipeline.
// (Exact round-9 mainloop — verified best.)
// ---------------------------------------------------------------------------
__global__ __launch_bounds__(256, 1)
void mm_fp16_kernel(const __half* __restrict__ A, const __half* __restrict__ B,
                    float* __restrict__ Cf, __half* __restrict__ Ch,
                    const float* __restrict__ bias, int N, int K, int flags)
{
    extern __shared__ char smem[];
    const uint32_t sb = smem_u32(smem);
    const int tid  = threadIdx.x;
    const int wid  = tid >> 5;
    const int lane = tid & 31;
    const int bm   = blockIdx.y * BM;
    const int bn   = blockIdx.x * BN;
    const int wm   = (wid >> 2) * 64;   // 2 warps in M
    const int wn   = (wid & 3) * 64;    // 4 warps in N
    const int ntiles = K / BK;

    // -------- producer addressing --------
    const int rowA = tid & 127;
    const int sgA  = tid >> 7;          // 0/1; covers segs sgA, sgA+2
    const __half* gA = A + (size_t)(bm + rowA) * K;
    const __half* gB = B + (size_t)(bn + tid) * K;   // 256 B-rows, 1 per thread
    const uint32_t doffA = (uint32_t)rowA * ROWB;
    const uint32_t doffB = (uint32_t)tid * ROWB;

    auto issue = [&](int kt, int s) {
        const uint32_t st = sb + (uint32_t)s * STG_BYTES;
        const size_t kof = (size_t)kt * BK;
#pragma unroll
        for (int qq = 0; qq < 2; qq++) {
            const int seg = sgA + qq * 2;
            cp16(st + STG_A + doffA + seg * 16, gA + kof + seg * 8);
        }
#pragma unroll
        for (int seg = 0; seg < 4; seg++)
            cp16(st + STG_B + doffB + seg * 16, gB + kof + seg * 8);
        asm volatile("cp.async.commit_group;" ::: "memory");
    };

    float acc[4][8][4];
#pragma unroll
    for (int i = 0; i < 4; i++)
#pragma unroll
        for (int j = 0; j < 8; j++)
#pragma unroll
            for (int l = 0; l < 4; l++) acc[i][j][l] = 0.f;

    issue(0, 0);
    issue(1, 1);
    issue(2, 2);

    // ldmatrix lane addressing
    const int arow  = lane & 15;
    const int acol8 = (lane >> 4) * 8;
    const int brow  = (lane & 7) + ((lane >> 4) << 3);
    const int bcol8 = ((lane >> 3) & 1) * 8;

    for (int kt = 0; kt < ntiles; kt++) {
        if (kt < ntiles - 2)
            asm volatile("cp.async.wait_group 2;" ::: "memory");
        else if (kt == ntiles - 2)
            asm volatile("cp.async.wait_group 1;" ::: "memory");
        else
            asm volatile("cp.async.wait_group 0;" ::: "memory");
        __syncthreads();

        const uint32_t stg = sb + (uint32_t)(kt % NSTG) * STG_BYTES;
#pragma unroll
        for (int ks = 0; ks < 2; ks++) {
            const int kb = ks * 16;
            uint32_t af[4][4], bf[4][4];
#pragma unroll
            for (int mt = 0; mt < 4; mt++) {
                const uint32_t off =
                    (uint32_t)((wm + mt * 16 + arow) * KSTRIDE + kb + acol8) * 2;
                ldsm4(af[mt], stg + STG_A + off);
            }
#pragma unroll
            for (int nt2 = 0; nt2 < 4; nt2++) {
                const uint32_t off =
                    (uint32_t)((wn + nt2 * 16 + brow) * KSTRIDE + kb + bcol8) * 2;
                ldsm4(bf[nt2], stg + STG_B + off);
            }
#pragma unroll
            for (int mt = 0; mt < 4; mt++)
#pragma unroll
                for (int nt = 0; nt < 8; nt++)
                    mma16816(acc[mt][nt], af[mt], &bf[nt >> 1][(nt & 1) * 2]);
        }
        if (kt + 3 < ntiles) issue(kt + 3, (kt + 3) % NSTG);
    }

    // -------- epilogue --------
    const int g = lane >> 2;
    const int t = lane & 3;
#pragma unroll
    for (int mt = 0; mt < 4; mt++)
#pragma unroll
        for (int nt = 0; nt < 8; nt++) {
            const int gcol = bn + wn + nt * 8 + t * 2;
            float b0 = 0.f, b1 = 0.f;
            if (bias) { b0 = __ldg(&bias[gcol]); b1 = __ldg(&bias[gcol + 1]); }
#pragma unroll
            for (int half_ = 0; half_ < 2; half_++) {
                const int grow = bm + wm + mt * 16 + g + half_ * 8;
                float v0 = acc[mt][nt][half_ * 2 + 0] + b0;
                float v1 = acc[mt][nt][half_ * 2 + 1] + b1;
                if (flags & 1) { v0 = fmaxf(v0, 0.f); v1 = fmaxf(v1, 0.f); }
                const size_t o = (size_t)grow * N + gcol;
                if (flags & 4)
                    *(float2*)(Cf + o) = make_float2(v0, v1);
                if (flags & 2)
                    *(__half2*)(Ch + o) =
                        __halves2half2(__float2half_rn(v0), __float2half_rn(v1));
            }
        }
}

// ---------------------------------------------------------------------------
// ALL weight transposes in ONE launch.  blockIdx.z selects the matrix.
// ---------------------------------------------------------------------------
__global__ void thalf_all_kernel(const float* __restrict__ Wq, const float* __restrict__ Wk,
                                 const float* __restrict__ Wv, const float* __restrict__ Wo,
                                 const float* __restrict__ W1, const float* __restrict__ W2,
                                 __half* __restrict__ wqkv, __half* __restrict__ wo,
                                 __half* __restrict__ w1, __half* __restrict__ w2)
{
    const float* W;
    __half* T;
    int Kd, Nd;
    switch (blockIdx.z) {
        case 0: W = Wq; T = wqkv;                           Kd = CDIM; Nd = CDIM; break;
        case 1: W = Wk; T = wqkv + (size_t)CDIM * CDIM;     Kd = CDIM; Nd = CDIM; break;
        case 2: W = Wv; T = wqkv + (size_t)2 * CDIM * CDIM; Kd = CDIM; Nd = CDIM; break;
        case 3: W = Wo; T = wo;                             Kd = CDIM; Nd = CDIM; break;
        case 4: W = W1; T = w1;                             Kd = CDIM; Nd = HDIM; break;
        default: W = W2; T = w2;                            Kd = HDIM; Nd = CDIM; break;
    }
    const int bx = blockIdx.x * 32;
    const int by = blockIdx.y * 32;
    if (bx >= Nd || by >= Kd) return;

    __shared__ float t[32][33];
    const int x = threadIdx.x, y0 = threadIdx.y;
#pragma unroll
    for (int dy = 0; dy < 32; dy += 8)
        t[y0 + dy][x] = W[(size_t)(by + y0 + dy) * Nd + bx + x];
    __syncthreads();
#pragma unroll
    for (int dy = 0; dy < 32; dy += 8)
        T[(size_t)(bx + y0 + dy) * Kd + by + x] = __float2half_rn(t[x][y0 + dy]);
}

// Elementwise fp32 -> fp16 (for x).
__global__ void tohalf_kernel(const float* __restrict__ in, __half* __restrict__ o,
                              int n4)
{
    int i = blockIdx.x * blockDim.x + threadIdx.x;
    if (i >= n4) return;
    float4 a = ((const float4*)in)[i];
    ((__half2*)o)[i * 2]     = __halves2half2(__float2half_rn(a.x), __float2half_rn(a.y));
    ((__half2*)o)[i * 2 + 1] = __halves2half2(__float2half_rn(a.z), __float2half_rn(a.w));
}

// ---------------------------------------------------------------------------
// Neighbor attention (K=8); fp16 qkv[M][3072] = q|k|v, fp32 math, fp16 ctx out.
// ---------------------------------------------------------------------------
__global__ __launch_bounds__(256)
void attn_kernel(const __half* __restrict__ qkv, const float* __restrict__ radj,
                 const int* __restrict__ inxs, __half* __restrict__ ctx)
{
    const int bt = blockIdx.x;
    const int b = bt >> 10;
    const int tid = threadIdx.x;
    const int wid = tid >> 5, lid = tid & 31;

    __shared__ float s_scores[KNEI];
    __shared__ int s_rows[KNEI];
    if (tid < KNEI) s_rows[tid] = b * TSEQ + inxs[(size_t)bt * KNEI + tid];
    __syncthreads();

    const uint4* qv = (const uint4*)(qkv + (size_t)bt * QKVLD);
    const uint4* kv = (const uint4*)(qkv + (size_t)s_rows[wid] * QKVLD + CDIM);
    float sum = 0.f;
#pragma unroll
    for (int e = lid; e < CDIM / 8; e += 32)
        sum += dot8(qv[e], kv[e]);
#pragma unroll
    for (int o = 16; o > 0; o >>= 1) sum += __shfl_xor_sync(0xffffffffu, sum, o);
    if (lid == 0)
        s_scores[wid] = sum * 0.03125f + radj[(size_t)bt * KNEI + wid];
    __syncthreads();

    float w[KNEI];
    float mx = s_scores[0];
#pragma unroll
    for (int j = 1; j < KNEI; j++) mx = fmaxf(mx, s_scores[j]);
    float den = 0.f;
#pragma unroll
    for (int j = 0; j < KNEI; j++) { w[j] = expf(s_scores[j] - mx); den += w[j]; }
    const float inv = 1.f / den;

    float a0 = 0.f, a1 = 0.f, a2 = 0.f, a3 = 0.f;
#pragma unroll
    for (int j = 0; j < KNEI; j++) {
        const uint2 vv =
            ((const uint2*)(qkv + (size_t)s_rows[j] * QKVLD + 2 * CDIM))[tid];
        const __half2* pv = (const __half2*)&vv;
        const float2 f0 = __half22float2(pv[0]);
        const float2 f1 = __half22float2(pv[1]);
        const float wj = w[j] * inv;
        a0 = fmaf(wj, f0.x, a0); a1 = fmaf(wj, f0.y, a1);
        a2 = fmaf(wj, f1.x, a2); a3 = fmaf(wj, f1.y, a3);
    }
    uint2 ov;
    ((__half2*)&ov)[0] = __halves2half2(__float2half_rn(a0), __float2half_rn(a1));
    ((__half2*)&ov)[1] = __halves2half2(__float2half_rn(a2), __float2half_rn(a3));
    ((uint2*)(ctx + (size_t)bt * CDIM))[tid] = ov;
}

// ---------------------------------------------------------------------------
// Fused residual (+optional relu) LayerNorm.
// Residual base: a32 (fp32) or a16 (fp16) — exactly one non-null.
// Residual branch hb is fp16.  Outputs: out32 (fp32) and/or out16 (fp16).
// ---------------------------------------------------------------------------
__global__ __launch_bounds__(256)
void ln_kernel(const float* __restrict__ a32, const __half* __restrict__ a16,
               const __half* __restrict__ hb,
               const float* __restrict__ g, const float* __restrict__ beta,
               float* __restrict__ out32, __half* __restrict__ out16, int relu_h)
{
    __shared__ float sh1[8], sh2[8];
    const int bt = blockIdx.x;
    const int tid = threadIdx.x;
    const int wid = tid >> 5, lid = tid & 31;
    const size_t base = (size_t)bt * CDIM;

    float4 z;
    if (a32) {
        z = ((const float4*)(a32 + base))[tid];
    } else {
        const uint2 av = ((const uint2*)(a16 + base))[tid];
        const __half2* pa = (const __half2*)&av;
        const float2 a01 = __half22float2(pa[0]);
        const float2 a23 = __half22float2(pa[1]);
        z = make_float4(a01.x, a01.y, a23.x, a23.y);
    }
    const uint2 hv = ((const uint2*)(hb + base))[tid];
    const __half2* ph = (const __half2*)&hv;
    const float2 h01 = __half22float2(ph[0]);
    const float2 h23 = __half22float2(ph[1]);
    float hx = h01.x, hy = h01.y, hz = h23.x, hw = h23.y;
    if (relu_h) {
        hx = fmaxf(hx, 0.f); hy = fmaxf(hy, 0.f);
        hz = fmaxf(hz, 0.f); hw = fmaxf(hw, 0.f);
    }
    z.x += hx; z.y += hy; z.z += hz; z.w += hw;

    float s = z.x + z.y + z.z + z.w;
    float ss = z.x * z.x + z.y * z.y + z.z * z.z + z.w * z.w;
#pragma unroll
    for (int o = 16; o > 0; o >>= 1) {
        s += __shfl_xor_sync(0xffffffffu, s, o);
        ss += __shfl_xor_sync(0xffffffffu, ss, o);
    }
    if (lid == 0) { sh1[wid] = s; sh2[wid] = ss; }
    __syncthreads();
    float ts = 0.f, tss = 0.f;
#pragma unroll
    for (int j = 0; j < 8; j++) { ts += sh1[j]; tss += sh2[j]; }

    const float mean = ts * (1.f / CDIM);
    const float var = tss * (1.f / CDIM) - mean * mean;
    const float rstd = rsqrtf(var + 1e-5f);

    const float4 gg = ((const float4*)g)[tid];
    const float4 bb = ((const float4*)beta)[tid];
    float4 o4;
    o4.x = (z.x - mean) * rstd * gg.x + bb.x;
    o4.y = (z.y - mean) * rstd * gg.y + bb.y;
    o4.z = (z.z - mean) * rstd * gg.z + bb.z;
    o4.w = (z.w - mean) * rstd * gg.w + bb.w;
    if (out32)
        ((float4*)(out32 + base))[tid] = o4;
    if (out16) {
        const size_t b2 = (size_t)bt * (CDIM / 2) + tid * 2;
        ((__half2*)out16)[b2] =
            __halves2half2(__float2half_rn(o4.x), __float2half_rn(o4.y));
        ((__half2*)out16)[b2 + 1] =
            __halves2half2(__float2half_rn(o4.z), __float2half_rn(o4.w));
    }
}

// ---------------------------------------------------------------------------
// Launch
// ---------------------------------------------------------------------------
extern "C" void kernel_launch(void* const* d_in, const int* in_sizes, int n_in,
                              void* d_out, int out_size)
{
    const float* x    = (const float*)d_in[0];
    const float* radj = (const float*)d_in[1];
    const int*   inxs = (const int*)  d_in[2];
    const float* Wq   = (const float*)d_in[3];
    const float* Wk   = (const float*)d_in[4];
    const float* Wv   = (const float*)d_in[5];
    const float* Wo   = (const float*)d_in[6];
    const float* ln1g = (const float*)d_in[7];
    const float* ln1b = (const float*)d_in[8];
    const float* W1   = (const float*)d_in[9];
    const float* b1   = (const float*)d_in[10];
    const float* W2   = (const float*)d_in[11];
    const float* b2   = (const float*)d_in[12];
    const float* ln2g = (const float*)d_in[13];
    const float* ln2b = (const float*)d_in[14];
    float* out = (float*)d_out;

    __half *qkv, *ctx, *h1, *yh, *f16, *xh, *hid, *wqkvh, *woh, *w1h, *w2h;
    cudaGetSymbolAddress((void**)&qkv, g_qkv);
    cudaGetSymbolAddress((void**)&ctx, g_ctx);
    cudaGetSymbolAddress((void**)&h1, g_h1);
    cudaGetSymbolAddress((void**)&yh, g_yh);
    cudaGetSymbolAddress((void**)&f16, g_f16);
    cudaGetSymbolAddress((void**)&xh, g_xh);
    cudaGetSymbolAddress((void**)&hid, g_hid);
    cudaGetSymbolAddress((void**)&wqkvh, g_wqkvh);
    cudaGetSymbolAddress((void**)&woh, g_woh);
    cudaGetSymbolAddress((void**)&w1h, g_w1h);
    cudaGetSymbolAddress((void**)&w2h, g_w2h);

    cudaFuncSetAttribute(mm_fp16_kernel,
                         cudaFuncAttributeMaxDynamicSharedMemorySize, MM_SMEM);

    const dim3 b256(256);

    thalf_all_kernel<<<dim3(HDIM / 32, HDIM / 32, 6), dim3(32, 8)>>>(
        Wq, Wk, Wv, Wo, W1, W2, wqkvh, woh, w1h, w2h);
    tohalf_kernel<<<(MDIM * CDIM / 4 + 255) / 256, b256>>>(x, xh, MDIM * CDIM / 4);

    const dim3 gQKV(QKVLD / BN, MDIM / BM);  // (12, 128)
    const dim3 gCC(CDIM / BN, MDIM / BM);    // (4, 128)
    const dim3 gCH(HDIM / BN, MDIM / BM);    // (6, 128)

    const __half* a16 = xh;
    for (int hop = 0; hop < 2; hop++) {
        mm_fp16_kernel<<<gQKV, 256, MM_SMEM>>>(a16, wqkvh, nullptr, qkv,
                                               nullptr, QKVLD, CDIM, 2);
        attn_kernel<<<MDIM, b256>>>(qkv, radj, inxs, ctx);
        mm_fp16_kernel<<<gCC, 256, MM_SMEM>>>(ctx, woh, nullptr, h1,
                                              nullptr, CDIM, CDIM, 2);
        a16 = h1;
    }

    // y = LN(x + relu(h))  -> fp16 only
    ln_kernel<<<MDIM, b256>>>(x, nullptr, h1, ln1g, ln1b, nullptr, yh, 1);
    // hid = relu(y @ W1 + b1)  -> fp16
    mm_fp16_kernel<<<gCH, 256, MM_SMEM>>>(yh, w1h, nullptr, hid, b1, HDIM, CDIM, 1 | 2);
    // f = hid @ W2 + b2  -> fp16
    mm_fp16_kernel<<<gCC, 256, MM_SMEM>>>(hid, w2h, nullptr, f16, b2, CDIM, HDIM, 2);
    // out = LN(y + f)  -> fp32 (d_out)
    ln_kernel<<<MDIM, b256>>>(nullptr, yh, f16, ln2g, ln2b, out, nullptr, 0);
}

// round 14
// speedup vs baseline: 1.3358x; 1.1673x over previous
#include <cuda_runtime.h>
#include <cuda_fp16.h>
#include <cstdint>
#include <math.h>

// ============================================================================
// ReasonNet via ldmatrix + mma.sync (HMMA), pure fp16 GEMMs (fp32 accum).
// Round 14: Wo folded into Wv (FIXED operand layout):
//   wvoT[m][n] = sum_j Wo^T[m][j] * Wv[n][j]   (B = plain row-major Wv fp16)
// Per-hop Wo GEMM eliminated.  GEMM work: 11 -> 9 C^2-units.
// B=16, T=1024, C=1024, K=8, H=1536.  M = B*T = 16384.
// ============================================================================

#define MDIM 16384
#define CDIM 1024
#define HDIM 1536
#define KNEI 8
#define TSEQ 1024
#define QKVLD 3072

#define BK 32
#define KSTRIDE 40                  // halfs per smem row (80B: aligned + LDSM conflict-free)
#define ROWB 80
#define BM 128
#define BN 256
#define STG_A 0
#define STG_B 10240                 // 128*80
#define STG_BYTES 30720             // + 256*80
#define NSTG 4
#define MM_SMEM (NSTG * STG_BYTES)  // 122880 bytes (1 CTA/SM)

// ---------------------------------------------------------------------------
// Scratch (static device globals; runtime allocation forbidden).
// ---------------------------------------------------------------------------
__device__ __half g_qkv [(size_t)MDIM * QKVLD];   // fused q|k|vo per hop (fp16)
__device__ __half g_h1  [(size_t)MDIM * CDIM];    // attn output = h (both hops)
__device__ __half g_yh  [(size_t)MDIM * CDIM];    // ln1 output (fp16)
__device__ __half g_f16 [(size_t)MDIM * CDIM];
__device__ __half g_xh  [(size_t)MDIM * CDIM];
__device__ __half g_hid [(size_t)MDIM * HDIM];
// Transposed fp16 weights: Wt[N][K].  QKV stacked: Wq^T | Wk^T | Wvo^T.
__device__ __half g_wqkvh[(size_t)QKVLD * CDIM];
__device__ __half g_wvh[(size_t)CDIM * CDIM];     // Wv row-major fp16 (for product)
__device__ __half g_woh[(size_t)CDIM * CDIM];     // Wo^T
__device__ __half g_w1h[(size_t)HDIM * CDIM];
__device__ __half g_w2h[(size_t)CDIM * HDIM];

// ---------------------------------------------------------------------------
// PTX helpers (sm_80-portable only)
// ---------------------------------------------------------------------------
__device__ __forceinline__ uint32_t smem_u32(const void* p) {
    uint32_t a;
    asm("{ .reg .u64 t; cvta.to.shared.u64 t, %1; cvt.u32.u64 %0, t; }"
        : "=r"(a) : "l"(p));
    return a;
}
__device__ __forceinline__ void cp16(uint32_t s, const void* g) {
    asm volatile("cp.async.cg.shared.global [%0], [%1], 16;" :: "r"(s), "l"(g) : "memory");
}
__device__ __forceinline__ void ldsm4(uint32_t* r, uint32_t addr) {
    asm volatile("ldmatrix.sync.aligned.m8n8.x4.shared.b16 {%0,%1,%2,%3}, [%4];"
                 : "=r"(r[0]), "=r"(r[1]), "=r"(r[2]), "=r"(r[3]) : "r"(addr));
}
__device__ __forceinline__ void mma16816(float* c, const uint32_t* a, const uint32_t* b) {
    asm volatile(
        "mma.sync.aligned.m16n8k16.row.col.f32.f16.f16.f32 "
        "{%0,%1,%2,%3}, {%4,%5,%6,%7}, {%8,%9}, {%0,%1,%2,%3};"
        : "+f"(c[0]), "+f"(c[1]), "+f"(c[2]), "+f"(c[3])
        : "r"(a[0]), "r"(a[1]), "r"(a[2]), "r"(a[3]), "r"(b[0]), "r"(b[1]));
}
// dot of 8 fp16 pairs (as uint4) accumulated in fp32
__device__ __forceinline__ float dot8(uint4 a, uint4 c) {
    const __half2* pa = (const __half2*)&a;
    const __half2* pc = (const __half2*)&c;
    float s = 0.f;
#pragma unroll
    for (int i = 0; i < 4; i++) {
        float2 fa = __half22float2(pa[i]);
        float2 fc = __half22float2(pc[i]);
        s += fa.x * fc.x + fa.y * fc.y;
    }
    return s;
}

// ---------------------------------------------------------------------------
// fp16 GEMM: C[M,N] = A[M,K] @ B[N,K]^T  (fp32 accumulate)
// flags: bit0 relu, bit1 write fp16 (Ch), bit2 write fp32 (Cf).
// 256 threads, 128x256 CTA tile, 64x64 warp tile, BK=32, 4-stage pipeline.
// (Round-9 mainloop — verified best.)
// ---------------------------------------------------------------------------
__global__ __launch_bounds__(256, 1)
void mm_fp16_kernel(const __half* __restrict__ A, const __half* __restrict__ B,
                    float* __restrict__ Cf, __half* __restrict__ Ch,
                    const float* __restrict__ bias, int N, int K, int flags)
{
    extern __shared__ char smem[];
    const uint32_t sb = smem_u32(smem);
    const int tid  = threadIdx.x;
    const int wid  = tid >> 5;
    const int lane = tid & 31;
    const int bm   = blockIdx.y * BM;
    const int bn   = blockIdx.x * BN;
    const int wm   = (wid >> 2) * 64;   // 2 warps in M
    const int wn   = (wid & 3) * 64;    // 4 warps in N
    const int ntiles = K / BK;

    // -------- producer addressing --------
    const int rowA = tid & 127;
    const int sgA  = tid >> 7;          // 0/1; covers segs sgA, sgA+2
    const __half* gA = A + (size_t)(bm + rowA) * K;
    const __half* gB = B + (size_t)(bn + tid) * K;   // 256 B-rows, 1 per thread
    const uint32_t doffA = (uint32_t)rowA * ROWB;
    const uint32_t doffB = (uint32_t)tid * ROWB;

    auto issue = [&](int kt, int s) {
        const uint32_t st = sb + (uint32_t)s * STG_BYTES;
        const size_t kof = (size_t)kt * BK;
#pragma unroll
        for (int qq = 0; qq < 2; qq++) {
            const int seg = sgA + qq * 2;
            cp16(st + STG_A + doffA + seg * 16, gA + kof + seg * 8);
        }
#pragma unroll
        for (int seg = 0; seg < 4; seg++)
            cp16(st + STG_B + doffB + seg * 16, gB + kof + seg * 8);
        asm volatile("cp.async.commit_group;" ::: "memory");
    };

    float acc[4][8][4];
#pragma unroll
    for (int i = 0; i < 4; i++)
#pragma unroll
        for (int j = 0; j < 8; j++)
#pragma unroll
            for (int l = 0; l < 4; l++) acc[i][j][l] = 0.f;

    issue(0, 0);
    issue(1, 1);
    issue(2, 2);

    // ldmatrix lane addressing
    const int arow  = lane & 15;
    const int acol8 = (lane >> 4) * 8;
    const int brow  = (lane & 7) + ((lane >> 4) << 3);
    const int bcol8 = ((lane >> 3) & 1) * 8;

    for (int kt = 0; kt < ntiles; kt++) {
        if (kt < ntiles - 2)
            asm volatile("cp.async.wait_group 2;" ::: "memory");
        else if (kt == ntiles - 2)
            asm volatile("cp.async.wait_group 1;" ::: "memory");
        else
            asm volatile("cp.async.wait_group 0;" ::: "memory");
        __syncthreads();

        const uint32_t stg = sb + (uint32_t)(kt % NSTG) * STG_BYTES;
#pragma unroll
        for (int ks = 0; ks < 2; ks++) {
            const int kb = ks * 16;
            uint32_t af[4][4], bf[4][4];
#pragma unroll
            for (int mt = 0; mt < 4; mt++) {
                const uint32_t off =
                    (uint32_t)((wm + mt * 16 + arow) * KSTRIDE + kb + acol8) * 2;
                ldsm4(af[mt], stg + STG_A + off);
            }
#pragma unroll
            for (int nt2 = 0; nt2 < 4; nt2++) {
                const uint32_t off =
                    (uint32_t)((wn + nt2 * 16 + brow) * KSTRIDE + kb + bcol8) * 2;
                ldsm4(bf[nt2], stg + STG_B + off);
            }
#pragma unroll
            for (int mt = 0; mt < 4; mt++)
#pragma unroll
                for (int nt = 0; nt < 8; nt++)
                    mma16816(acc[mt][nt], af[mt], &bf[nt >> 1][(nt & 1) * 2]);
        }
        if (kt + 3 < ntiles) issue(kt + 3, (kt + 3) % NSTG);
    }

    // -------- epilogue --------
    const int g = lane >> 2;
    const int t = lane & 3;
#pragma unroll
    for (int mt = 0; mt < 4; mt++)
#pragma unroll
        for (int nt = 0; nt < 8; nt++) {
            const int gcol = bn + wn + nt * 8 + t * 2;
            float b0 = 0.f, b1 = 0.f;
            if (bias) { b0 = __ldg(&bias[gcol]); b1 = __ldg(&bias[gcol + 1]); }
#pragma unroll
            for (int half_ = 0; half_ < 2; half_++) {
                const int grow = bm + wm + mt * 16 + g + half_ * 8;
                float v0 = acc[mt][nt][half_ * 2 + 0] + b0;
                float v1 = acc[mt][nt][half_ * 2 + 1] + b1;
                if (flags & 1) { v0 = fmaxf(v0, 0.f); v1 = fmaxf(v1, 0.f); }
                const size_t o = (size_t)grow * N + gcol;
                if (flags & 4)
                    *(float2*)(Cf + o) = make_float2(v0, v1);
                if (flags & 2)
                    *(__half2*)(Ch + o) =
                        __halves2half2(__float2half_rn(v0), __float2half_rn(v1));
            }
        }
}

// ---------------------------------------------------------------------------
// Weight transposes in ONE launch (Wq, Wk, Wo, W1, W2).  Wv is converted
// WITHOUT transpose by tohalf_kernel (needed row-major for the Wvo product).
// ---------------------------------------------------------------------------
__global__ void thalf_all_kernel(const float* __restrict__ Wq, const float* __restrict__ Wk,
                                 const float* __restrict__ Wo,
                                 const float* __restrict__ W1, const float* __restrict__ W2,
                                 __half* __restrict__ wqkv, __half* __restrict__ wo,
                                 __half* __restrict__ w1, __half* __restrict__ w2)
{
    const float* W;
    __half* T;
    int Kd, Nd;
    switch (blockIdx.z) {
        case 0: W = Wq; T = wqkv;                           Kd = CDIM; Nd = CDIM; break;
        case 1: W = Wk; T = wqkv + (size_t)CDIM * CDIM;     Kd = CDIM; Nd = CDIM; break;
        case 2: W = Wo; T = wo;                             Kd = CDIM; Nd = CDIM; break;
        case 3: W = W1; T = w1;                             Kd = CDIM; Nd = HDIM; break;
        default: W = W2; T = w2;                            Kd = HDIM; Nd = CDIM; break;
    }
    const int bx = blockIdx.x * 32;
    const int by = blockIdx.y * 32;
    if (bx >= Nd || by >= Kd) return;

    __shared__ float t[32][33];
    const int x = threadIdx.x, y0 = threadIdx.y;
#pragma unroll
    for (int dy = 0; dy < 32; dy += 8)
        t[y0 + dy][x] = W[(size_t)(by + y0 + dy) * Nd + bx + x];
    __syncthreads();
#pragma unroll
    for (int dy = 0; dy < 32; dy += 8)
        T[(size_t)(bx + y0 + dy) * Kd + by + x] = __float2half_rn(t[x][y0 + dy]);
}

// Elementwise fp32 -> fp16 (no transpose).
__global__ void tohalf_kernel(const float* __restrict__ in, __half* __restrict__ o,
                              int n4)
{
    int i = blockIdx.x * blockDim.x + threadIdx.x;
    if (i >= n4) return;
    float4 a = ((const float4*)in)[i];
    ((__half2*)o)[i * 2]     = __halves2half2(__float2half_rn(a.x), __float2half_rn(a.y));
    ((__half2*)o)[i * 2 + 1] = __halves2half2(__float2half_rn(a.z), __float2half_rn(a.w));
}

// ---------------------------------------------------------------------------
// Neighbor attention (K=8); fp16 qkv[M][3072] = q|k|vo.  Output = h directly
// (Wo already folded into vo).  fp32 math inside, fp16 out.
// ---------------------------------------------------------------------------
__global__ __launch_bounds__(256)
void attn_kernel(const __half* __restrict__ qkv, const float* __restrict__ radj,
                 const int* __restrict__ inxs, __half* __restrict__ hout)
{
    const int bt = blockIdx.x;
    const int b = bt >> 10;
    const int tid = threadIdx.x;
    const int wid = tid >> 5, lid = tid & 31;

    __shared__ float s_scores[KNEI];
    __shared__ int s_rows[KNEI];
    if (tid < KNEI) s_rows[tid] = b * TSEQ + inxs[(size_t)bt * KNEI + tid];
    __syncthreads();

    const uint4* qv = (const uint4*)(qkv + (size_t)bt * QKVLD);
    const uint4* kv = (const uint4*)(qkv + (size_t)s_rows[wid] * QKVLD + CDIM);
    float sum = 0.f;
#pragma unroll
    for (int e = lid; e < CDIM / 8; e += 32)
        sum += dot8(qv[e], kv[e]);
#pragma unroll
    for (int o = 16; o > 0; o >>= 1) sum += __shfl_xor_sync(0xffffffffu, sum, o);
    if (lid == 0)
        s_scores[wid] = sum * 0.03125f + radj[(size_t)bt * KNEI + wid];
    __syncthreads();

    float w[KNEI];
    float mx = s_scores[0];
#pragma unroll
    for (int j = 1; j < KNEI; j++) mx = fmaxf(mx, s_scores[j]);
    float den = 0.f;
#pragma unroll
    for (int j = 0; j < KNEI; j++) { w[j] = expf(s_scores[j] - mx); den += w[j]; }
    const float inv = 1.f / den;

    float a0 = 0.f, a1 = 0.f, a2 = 0.f, a3 = 0.f;
#pragma unroll
    for (int j = 0; j < KNEI; j++) {
        const uint2 vv =
            ((const uint2*)(qkv + (size_t)s_rows[j] * QKVLD + 2 * CDIM))[tid];
        const __half2* pv = (const __half2*)&vv;
        const float2 f0 = __half22float2(pv[0]);
        const float2 f1 = __half22float2(pv[1]);
        const float wj = w[j] * inv;
        a0 = fmaf(wj, f0.x, a0); a1 = fmaf(wj, f0.y, a1);
        a2 = fmaf(wj, f1.x, a2); a3 = fmaf(wj, f1.y, a3);
    }
    uint2 ov;
    ((__half2*)&ov)[0] = __halves2half2(__float2half_rn(a0), __float2half_rn(a1));
    ((__half2*)&ov)[1] = __halves2half2(__float2half_rn(a2), __float2half_rn(a3));
    ((uint2*)(hout + (size_t)bt * CDIM))[tid] = ov;
}

// ---------------------------------------------------------------------------
// Fused residual (+optional relu) LayerNorm.
// Residual base: a32 (fp32) or a16 (fp16) — exactly one non-null.
// Residual branch hb is fp16.  Outputs: out32 (fp32) and/or out16 (fp16).
// ---------------------------------------------------------------------------
__global__ __launch_bounds__(256)
void ln_kernel(const float* __restrict__ a32, const __half* __restrict__ a16,
               const __half* __restrict__ hb,
               const float* __restrict__ g, const float* __restrict__ beta,
               float* __restrict__ out32, __half* __restrict__ out16, int relu_h)
{
    __shared__ float sh1[8], sh2[8];
    const int bt = blockIdx.x;
    const int tid = threadIdx.x;
    const int wid = tid >> 5, lid = tid & 31;
    const size_t base = (size_t)bt * CDIM;

    float4 z;
    if (a32) {
        z = ((const float4*)(a32 + base))[tid];
    } else {
        const uint2 av = ((const uint2*)(a16 + base))[tid];
        const __half2* pa = (const __half2*)&av;
        const float2 a01 = __half22float2(pa[0]);
        const float2 a23 = __half22float2(pa[1]);
        z = make_float4(a01.x, a01.y, a23.x, a23.y);
    }
    const uint2 hv = ((const uint2*)(hb + base))[tid];
    const __half2* ph = (const __half2*)&hv;
    const float2 h01 = __half22float2(ph[0]);
    const float2 h23 = __half22float2(ph[1]);
    float hx = h01.x, hy = h01.y, hz = h23.x, hw = h23.y;
    if (relu_h) {
        hx = fmaxf(hx, 0.f); hy = fmaxf(hy, 0.f);
        hz = fmaxf(hz, 0.f); hw = fmaxf(hw, 0.f);
    }
    z.x += hx; z.y += hy; z.z += hz; z.w += hw;

    float s = z.x + z.y + z.z + z.w;
    float ss = z.x * z.x + z.y * z.y + z.z * z.z + z.w * z.w;
#pragma unroll
    for (int o = 16; o > 0; o >>= 1) {
        s += __shfl_xor_sync(0xffffffffu, s, o);
        ss += __shfl_xor_sync(0xffffffffu, ss, o);
    }
    if (lid == 0) { sh1[wid] = s; sh2[wid] = ss; }
    __syncthreads();
    float ts = 0.f, tss = 0.f;
#pragma unroll
    for (int j = 0; j < 8; j++) { ts += sh1[j]; tss += sh2[j]; }

    const float mean = ts * (1.f / CDIM);
    const float var = tss * (1.f / CDIM) - mean * mean;
    const float rstd = rsqrtf(var + 1e-5f);

    const float4 gg = ((const float4*)g)[tid];
    const float4 bb = ((const float4*)beta)[tid];
    float4 o4;
    o4.x = (z.x - mean) * rstd * gg.x + bb.x;
    o4.y = (z.y - mean) * rstd * gg.y + bb.y;
    o4.z = (z.z - mean) * rstd * gg.z + bb.z;
    o4.w = (z.w - mean) * rstd * gg.w + bb.w;
    if (out32)
        ((float4*)(out32 + base))[tid] = o4;
    if (out16) {
        const size_t b2 = (size_t)bt * (CDIM / 2) + tid * 2;
        ((__half2*)out16)[b2] =
            __halves2half2(__float2half_rn(o4.x), __float2half_rn(o4.y));
        ((__half2*)out16)[b2 + 1] =
            __halves2half2(__float2half_rn(o4.z), __float2half_rn(o4.w));
    }
}

// ---------------------------------------------------------------------------
// Launch
// ---------------------------------------------------------------------------
extern "C" void kernel_launch(void* const* d_in, const int* in_sizes, int n_in,
                              void* d_out, int out_size)
{
    const float* x    = (const float*)d_in[0];
    const float* radj = (const float*)d_in[1];
    const int*   inxs = (const int*)  d_in[2];
    const float* Wq   = (const float*)d_in[3];
    const float* Wk   = (const float*)d_in[4];
    const float* Wv   = (const float*)d_in[5];
    const float* Wo   = (const float*)d_in[6];
    const float* ln1g = (const float*)d_in[7];
    const float* ln1b = (const float*)d_in[8];
    const float* W1   = (const float*)d_in[9];
    const float* b1   = (const float*)d_in[10];
    const float* W2   = (const float*)d_in[11];
    const float* b2   = (const float*)d_in[12];
    const float* ln2g = (const float*)d_in[13];
    const float* ln2b = (const float*)d_in[14];
    float* out = (float*)d_out;

    __half *qkv, *h1, *yh, *f16, *xh, *hid, *wqkvh, *wvh, *woh, *w1h, *w2h;
    cudaGetSymbolAddress((void**)&qkv, g_qkv);
    cudaGetSymbolAddress((void**)&h1, g_h1);
    cudaGetSymbolAddress((void**)&yh, g_yh);
    cudaGetSymbolAddress((void**)&f16, g_f16);
    cudaGetSymbolAddress((void**)&xh, g_xh);
    cudaGetSymbolAddress((void**)&hid, g_hid);
    cudaGetSymbolAddress((void**)&wqkvh, g_wqkvh);
    cudaGetSymbolAddress((void**)&wvh, g_wvh);
    cudaGetSymbolAddress((void**)&woh, g_woh);
    cudaGetSymbolAddress((void**)&w1h, g_w1h);
    cudaGetSymbolAddress((void**)&w2h, g_w2h);

    cudaFuncSetAttribute(mm_fp16_kernel,
                         cudaFuncAttributeMaxDynamicSharedMemorySize, MM_SMEM);

    const dim3 b256(256);

    // Weight prep: transposes (Wq,Wk,Wo,W1,W2), plain fp16 Wv, x -> fp16.
    thalf_all_kernel<<<dim3(HDIM / 32, HDIM / 32, 5), dim3(32, 8)>>>(
        Wq, Wk, Wo, W1, W2, wqkvh, woh, w1h, w2h);
    tohalf_kernel<<<(CDIM * CDIM / 4 + 255) / 256, b256>>>(Wv, wvh, CDIM * CDIM / 4);
    tohalf_kernel<<<(MDIM * CDIM / 4 + 255) / 256, b256>>>(x, xh, MDIM * CDIM / 4);
    // wvoT[m][n] = sum_j Wo^T[m][j] * Wv[n][j] = Wvo^T  (into QKV stack block 3)
    mm_fp16_kernel<<<dim3(CDIM / BN, CDIM / BM), 256, MM_SMEM>>>(
        woh, wvh, nullptr, wqkvh + (size_t)2 * CDIM * CDIM, nullptr, CDIM, CDIM, 2);

    const dim3 gQKV(QKVLD / BN, MDIM / BM);  // (12, 128)
    const dim3 gCC(CDIM / BN, MDIM / BM);    // (4, 128)
    const dim3 gCH(HDIM / BN, MDIM / BM);    // (6, 128)

    const __half* a16 = xh;
    for (int hop = 0; hop < 2; hop++) {
        // q|k|vo = a @ [Wq | Wk | Wvo]^T
        mm_fp16_kernel<<<gQKV, 256, MM_SMEM>>>(a16, wqkvh, nullptr, qkv,
                                               nullptr, QKVLD, CDIM, 2);
        // attn produces h directly (Wo folded into vo)
        attn_kernel<<<MDIM, b256>>>(qkv, radj, inxs, h1);
        a16 = h1;
    }

    // y = LN(x + relu(h))  -> fp16 only
    ln_kernel<<<MDIM, b256>>>(x, nullptr, h1, ln1g, ln1b, nullptr, yh, 1);
    // hid = relu(y @ W1 + b1)  -> fp16
    mm_fp16_kernel<<<gCH, 256, MM_SMEM>>>(yh, w1h, nullptr, hid, b1, HDIM, CDIM, 1 | 2);
    // f = hid @ W2 + b2  -> fp16
    mm_fp16_kernel<<<gCC, 256, MM_SMEM>>>(hid, w2h, nullptr, f16, b2, CDIM, HDIM, 2);
    // out = LN(y + f)  -> fp32 (d_out)
    ln_kernel<<<MDIM, b256>>>(nullptr, yh, f16, ln2g, ln2b, out, nullptr, 0);
}

// round 16
// speedup vs baseline: 1.3685x; 1.0245x over previous
#include <cuda_runtime.h>
#include <cuda_fp16.h>
#include <cstdint>
#include <math.h>

// ============================================================================
// ReasonNet via ldmatrix + mma.sync (HMMA), pure fp16 GEMMs (fp32 accum).
// Round 16: round-14 verified config (Wvo fold only) +
//   - prep Wvo product split-K x4 (1 wave instead of 12.5% occupancy)
//   - FFN2 split-K x2, fp32 partials summed inside ln2 (bias in partial 0)
// B=16, T=1024, C=1024, K=8, H=1536.  M = B*T = 16384.
// ============================================================================

#define MDIM 16384
#define CDIM 1024
#define HDIM 1536
#define KNEI 8
#define TSEQ 1024
#define QKVLD 3072

#define BK 32
#define KSTRIDE 40                  // halfs per smem row (80B: aligned + LDSM conflict-free)
#define ROWB 80
#define BM 128
#define BN 256
#define STG_A 0
#define STG_B 10240                 // 128*80
#define STG_BYTES 30720             // + 256*80
#define NSTG 4
#define MM_SMEM (NSTG * STG_BYTES)  // 122880 bytes (1 CTA/SM)

// ---------------------------------------------------------------------------
// Scratch (static device globals; runtime allocation forbidden).
// ---------------------------------------------------------------------------
__device__ __half g_qkv [(size_t)MDIM * QKVLD];   // fused q|k|vo per hop (fp16)
__device__ __half g_h1  [(size_t)MDIM * CDIM];    // attn output = h (both hops)
__device__ __half g_yh  [(size_t)MDIM * CDIM];    // ln1 output (fp16)
__device__ __half g_xh  [(size_t)MDIM * CDIM];
__device__ __half g_hid [(size_t)MDIM * HDIM];
__device__ float  g_fpa [(size_t)MDIM * CDIM];    // FFN2 split-K partial 0 (fp32)
__device__ float  g_fpb [(size_t)MDIM * CDIM];    // FFN2 split-K partial 1 (fp32)
__device__ float  g_wp  [(size_t)4 * CDIM * CDIM];// Wvo prep partials (fp32)
// fp16 weights.  QKV stacked: Wq^T | Wk^T | Wvo^T.
__device__ __half g_wqkvh[(size_t)QKVLD * CDIM];
__device__ __half g_wvh[(size_t)CDIM * CDIM];     // Wv row-major fp16
__device__ __half g_woh[(size_t)CDIM * CDIM];     // Wo^T fp16
__device__ __half g_w1h[(size_t)HDIM * CDIM];
__device__ __half g_w2h[(size_t)CDIM * HDIM];

// ---------------------------------------------------------------------------
// PTX helpers (sm_80-portable only)
// ---------------------------------------------------------------------------
__device__ __forceinline__ uint32_t smem_u32(const void* p) {
    uint32_t a;
    asm("{ .reg .u64 t; cvta.to.shared.u64 t, %1; cvt.u32.u64 %0, t; }"
        : "=r"(a) : "l"(p));
    return a;
}
__device__ __forceinline__ void cp16(uint32_t s, const void* g) {
    asm volatile("cp.async.cg.shared.global [%0], [%1], 16;" :: "r"(s), "l"(g) : "memory");
}
__device__ __forceinline__ void ldsm4(uint32_t* r, uint32_t addr) {
    asm volatile("ldmatrix.sync.aligned.m8n8.x4.shared.b16 {%0,%1,%2,%3}, [%4];"
                 : "=r"(r[0]), "=r"(r[1]), "=r"(r[2]), "=r"(r[3]) : "r"(addr));
}
__device__ __forceinline__ void mma16816(float* c, const uint32_t* a, const uint32_t* b) {
    asm volatile(
        "mma.sync.aligned.m16n8k16.row.col.f32.f16.f16.f32 "
        "{%0,%1,%2,%3}, {%4,%5,%6,%7}, {%8,%9}, {%0,%1,%2,%3};"
        : "+f"(c[0]), "+f"(c[1]), "+f"(c[2]), "+f"(c[3])
        : "r"(a[0]), "r"(a[1]), "r"(a[2]), "r"(a[3]), "r"(b[0]), "r"(b[1]));
}
__device__ __forceinline__ float dot8(uint4 a, uint4 c) {
    const __half2* pa = (const __half2*)&a;
    const __half2* pc = (const __half2*)&c;
    float s = 0.f;
#pragma unroll
    for (int i = 0; i < 4; i++) {
        float2 fa = __half22float2(pa[i]);
        float2 fc = __half22float2(pc[i]);
        s += fa.x * fc.x + fa.y * fc.y;
    }
    return s;
}

// ---------------------------------------------------------------------------
// GEMM device body: C[M,N] = A[M,0:K] @ B[N,0:K]^T, rows strided by lda.
// flags: bit0 relu, bit1 write fp16 (Ch), bit2 write fp32 (Cf).
// 256 threads, 128x256 CTA tile, 64x64 warp tile, BK=32, 4-stage pipeline.
// (Round-9 mainloop — verified best.)
// ---------------------------------------------------------------------------
__device__ __forceinline__ void mm_body(const __half* __restrict__ A,
                                        const __half* __restrict__ B,
                                        float* __restrict__ Cf, __half* __restrict__ Ch,
                                        const float* __restrict__ bias,
                                        int N, int K, int lda, int flags, char* smem)
{
    const uint32_t sb = smem_u32(smem);
    const int tid  = threadIdx.x;
    const int wid  = tid >> 5;
    const int lane = tid & 31;
    const int bm   = blockIdx.y * BM;
    const int bn   = blockIdx.x * BN;
    const int wm   = (wid >> 2) * 64;
    const int wn   = (wid & 3) * 64;
    const int ntiles = K / BK;

    const int rowA = tid & 127;
    const int sgA  = tid >> 7;
    const __half* gA = A + (size_t)(bm + rowA) * lda;
    const __half* gB = B + (size_t)(bn + tid) * lda;
    const uint32_t doffA = (uint32_t)rowA * ROWB;
    const uint32_t doffB = (uint32_t)tid * ROWB;

    auto issue = [&](int kt, int s) {
        const uint32_t st = sb + (uint32_t)s * STG_BYTES;
        const size_t kof = (size_t)kt * BK;
#pragma unroll
        for (int qq = 0; qq < 2; qq++) {
            const int seg = sgA + qq * 2;
            cp16(st + STG_A + doffA + seg * 16, gA + kof + seg * 8);
        }
#pragma unroll
        for (int seg = 0; seg < 4; seg++)
            cp16(st + STG_B + doffB + seg * 16, gB + kof + seg * 8);
        asm volatile("cp.async.commit_group;" ::: "memory");
    };

    float acc[4][8][4];
#pragma unroll
    for (int i = 0; i < 4; i++)
#pragma unroll
        for (int j = 0; j < 8; j++)
#pragma unroll
            for (int l = 0; l < 4; l++) acc[i][j][l] = 0.f;

    issue(0, 0);
    issue(1, 1);
    issue(2, 2);

    const int arow  = lane & 15;
    const int acol8 = (lane >> 4) * 8;
    const int brow  = (lane & 7) + ((lane >> 4) << 3);
    const int bcol8 = ((lane >> 3) & 1) * 8;

    for (int kt = 0; kt < ntiles; kt++) {
        if (kt < ntiles - 2)
            asm volatile("cp.async.wait_group 2;" ::: "memory");
        else if (kt == ntiles - 2)
            asm volatile("cp.async.wait_group 1;" ::: "memory");
        else
            asm volatile("cp.async.wait_group 0;" ::: "memory");
        __syncthreads();

        const uint32_t stg = sb + (uint32_t)(kt % NSTG) * STG_BYTES;
#pragma unroll
        for (int ks = 0; ks < 2; ks++) {
            const int kb = ks * 16;
            uint32_t af[4][4], bf[4][4];
#pragma unroll
            for (int mt = 0; mt < 4; mt++) {
                const uint32_t off =
                    (uint32_t)((wm + mt * 16 + arow) * KSTRIDE + kb + acol8) * 2;
                ldsm4(af[mt], stg + STG_A + off);
            }
#pragma unroll
            for (int nt2 = 0; nt2 < 4; nt2++) {
                const uint32_t off =
                    (uint32_t)((wn + nt2 * 16 + brow) * KSTRIDE + kb + bcol8) * 2;
                ldsm4(bf[nt2], stg + STG_B + off);
            }
#pragma unroll
            for (int mt = 0; mt < 4; mt++)
#pragma unroll
                for (int nt = 0; nt < 8; nt++)
                    mma16816(acc[mt][nt], af[mt], &bf[nt >> 1][(nt & 1) * 2]);
        }
        if (kt + 3 < ntiles) issue(kt + 3, (kt + 3) % NSTG);
    }

    const int g = lane >> 2;
    const int t = lane & 3;
#pragma unroll
    for (int mt = 0; mt < 4; mt++)
#pragma unroll
        for (int nt = 0; nt < 8; nt++) {
            const int gcol = bn + wn + nt * 8 + t * 2;
            float b0 = 0.f, b1 = 0.f;
            if (bias) { b0 = __ldg(&bias[gcol]); b1 = __ldg(&bias[gcol + 1]); }
#pragma unroll
            for (int half_ = 0; half_ < 2; half_++) {
                const int grow = bm + wm + mt * 16 + g + half_ * 8;
                float v0 = acc[mt][nt][half_ * 2 + 0] + b0;
                float v1 = acc[mt][nt][half_ * 2 + 1] + b1;
                if (flags & 1) { v0 = fmaxf(v0, 0.f); v1 = fmaxf(v1, 0.f); }
                const size_t o = (size_t)grow * N + gcol;
                if (flags & 4)
                    *(float2*)(Cf + o) = make_float2(v0, v1);
                if (flags & 2)
                    *(__half2*)(Ch + o) =
                        __halves2half2(__float2half_rn(v0), __float2half_rn(v1));
            }
        }
}

__global__ __launch_bounds__(256, 1)
void mm_fp16_kernel(const __half* __restrict__ A, const __half* __restrict__ B,
                    float* __restrict__ Cf, __half* __restrict__ Ch,
                    const float* __restrict__ bias, int N, int K, int flags)
{
    extern __shared__ char smem[];
    mm_body(A, B, Cf, Ch, bias, N, K, K, flags, smem);
}

// Prep Wvo product, split-K x4:  z handles K range [z*256, z*256+256).
// partial_z[m][n] = sum_{j in range} Wo^T[m][j] * Wv[n][j]   (fp32 out)
__global__ __launch_bounds__(256, 1)
void mm_prep_kernel(const __half* __restrict__ A, const __half* __restrict__ B,
                    float* __restrict__ P)
{
    extern __shared__ char smem[];
    const int z = blockIdx.z;
    mm_body(A + z * 256, B + z * 256, P + (size_t)z * CDIM * CDIM, nullptr,
            nullptr, CDIM, 256, CDIM, 4, smem);
}

// Reduce 4 fp32 partials -> fp16 Wvo^T.
__global__ void reduce4_kernel(const float* __restrict__ P, __half* __restrict__ O)
{
    const size_t n = (size_t)CDIM * CDIM;
    size_t i = (size_t)(blockIdx.x * blockDim.x + threadIdx.x) * 2;
    float2 a = *(const float2*)(P + i);
    float2 b = *(const float2*)(P + n + i);
    float2 c = *(const float2*)(P + 2 * n + i);
    float2 d = *(const float2*)(P + 3 * n + i);
    const float v0 = a.x + b.x + c.x + d.x;
    const float v1 = a.y + b.y + c.y + d.y;
    *(__half2*)(O + i) = __halves2half2(__float2half_rn(v0), __float2half_rn(v1));
}

// FFN2 split-K x2: z=0 covers K [0,768) WITH bias, z=1 covers [768,1536).
__global__ __launch_bounds__(256, 1)
void mm_f2_kernel(const __half* __restrict__ A, const __half* __restrict__ B,
                  float* __restrict__ P0, float* __restrict__ P1,
                  const float* __restrict__ bias)
{
    extern __shared__ char smem[];
    const int z = blockIdx.z;
    const int koff = z * (HDIM / 2);
    mm_body(A + koff, B + koff, z == 0 ? P0 : P1, nullptr,
            z == 0 ? bias : nullptr, CDIM, HDIM / 2, HDIM, 4, smem);
}

// ---------------------------------------------------------------------------
// Weight transposes in ONE launch (Wq, Wk, Wo, W1, W2); z selects.
// ---------------------------------------------------------------------------
__global__ void thalf_all_kernel(const float* __restrict__ Wq, const float* __restrict__ Wk,
                                 const float* __restrict__ Wo,
                                 const float* __restrict__ W1, const float* __restrict__ W2,
                                 __half* __restrict__ wqkv, __half* __restrict__ wo,
                                 __half* __restrict__ w1, __half* __restrict__ w2)
{
    const float* W;
    __half* T;
    int Kd, Nd;
    switch (blockIdx.z) {
        case 0: W = Wq; T = wqkv;                           Kd = CDIM; Nd = CDIM; break;
        case 1: W = Wk; T = wqkv + (size_t)CDIM * CDIM;     Kd = CDIM; Nd = CDIM; break;
        case 2: W = Wo; T = wo;                             Kd = CDIM; Nd = CDIM; break;
        case 3: W = W1; T = w1;                             Kd = CDIM; Nd = HDIM; break;
        default: W = W2; T = w2;                            Kd = HDIM; Nd = CDIM; break;
    }
    const int bx = blockIdx.x * 32;
    const int by = blockIdx.y * 32;
    if (bx >= Nd || by >= Kd) return;

    __shared__ float t[32][33];
    const int x = threadIdx.x, y0 = threadIdx.y;
#pragma unroll
    for (int dy = 0; dy < 32; dy += 8)
        t[y0 + dy][x] = W[(size_t)(by + y0 + dy) * Nd + bx + x];
    __syncthreads();
#pragma unroll
    for (int dy = 0; dy < 32; dy += 8)
        T[(size_t)(bx + y0 + dy) * Kd + by + x] = __float2half_rn(t[x][y0 + dy]);
}

// Elementwise fp32 -> fp16 (no transpose).
__global__ void tohalf_kernel(const float* __restrict__ in, __half* __restrict__ o,
                              int n4)
{
    int i = blockIdx.x * blockDim.x + threadIdx.x;
    if (i >= n4) return;
    float4 a = ((const float4*)in)[i];
    ((__half2*)o)[i * 2]     = __halves2half2(__float2half_rn(a.x), __float2half_rn(a.y));
    ((__half2*)o)[i * 2 + 1] = __halves2half2(__float2half_rn(a.z), __float2half_rn(a.w));
}

// ---------------------------------------------------------------------------
// Neighbor attention (K=8); fp16 qkv[M][3072] = q|k|vo.  Output = h directly
// (Wo folded into vo).  fp32 math inside, fp16 out.
// ---------------------------------------------------------------------------
__global__ __launch_bounds__(256)
void attn_kernel(const __half* __restrict__ qkv, const float* __restrict__ radj,
                 const int* __restrict__ inxs, __half* __restrict__ hout)
{
    const int bt = blockIdx.x;
    const int b = bt >> 10;
    const int tid = threadIdx.x;
    const int wid = tid >> 5, lid = tid & 31;

    __shared__ float s_scores[KNEI];
    __shared__ int s_rows[KNEI];
    if (tid < KNEI) s_rows[tid] = b * TSEQ + inxs[(size_t)bt * KNEI + tid];
    __syncthreads();

    const uint4* qv = (const uint4*)(qkv + (size_t)bt * QKVLD);
    const uint4* kv = (const uint4*)(qkv + (size_t)s_rows[wid] * QKVLD + CDIM);
    float sum = 0.f;
#pragma unroll
    for (int e = lid; e < CDIM / 8; e += 32)
        sum += dot8(qv[e], kv[e]);
#pragma unroll
    for (int o = 16; o > 0; o >>= 1) sum += __shfl_xor_sync(0xffffffffu, sum, o);
    if (lid == 0)
        s_scores[wid] = sum * 0.03125f + radj[(size_t)bt * KNEI + wid];
    __syncthreads();

    float w[KNEI];
    float mx = s_scores[0];
#pragma unroll
    for (int j = 1; j < KNEI; j++) mx = fmaxf(mx, s_scores[j]);
    float den = 0.f;
#pragma unroll
    for (int j = 0; j < KNEI; j++) { w[j] = expf(s_scores[j] - mx); den += w[j]; }
    const float inv = 1.f / den;

    float a0 = 0.f, a1 = 0.f, a2 = 0.f, a3 = 0.f;
#pragma unroll
    for (int j = 0; j < KNEI; j++) {
        const uint2 vv =
            ((const uint2*)(qkv + (size_t)s_rows[j] * QKVLD + 2 * CDIM))[tid];
        const __half2* pv = (const __half2*)&vv;
        const float2 f0 = __half22float2(pv[0]);
        const float2 f1 = __half22float2(pv[1]);
        const float wj = w[j] * inv;
        a0 = fmaf(wj, f0.x, a0); a1 = fmaf(wj, f0.y, a1);
        a2 = fmaf(wj, f1.x, a2); a3 = fmaf(wj, f1.y, a3);
    }
    uint2 ov;
    ((__half2*)&ov)[0] = __halves2half2(__float2half_rn(a0), __float2half_rn(a1));
    ((__half2*)&ov)[1] = __halves2half2(__float2half_rn(a2), __float2half_rn(a3));
    ((uint2*)(hout + (size_t)bt * CDIM))[tid] = ov;
}

// ---------------------------------------------------------------------------
// Fused residual (+optional relu) LayerNorm.
// Base: a32 (fp32) or a16 (fp16).  Branch: hb16, OR hb32a+hb32b (fp32 partials).
// Outputs: out32 and/or out16.
// ---------------------------------------------------------------------------
__global__ __launch_bounds__(256)
void ln_kernel(const float* __restrict__ a32, const __half* __restrict__ a16,
               const __half* __restrict__ hb16,
               const float* __restrict__ hb32a, const float* __restrict__ hb32b,
               const float* __restrict__ g, const float* __restrict__ beta,
               float* __restrict__ out32, __half* __restrict__ out16, int relu_h)
{
    __shared__ float sh1[8], sh2[8];
    const int bt = blockIdx.x;
    const int tid = threadIdx.x;
    const int wid = tid >> 5, lid = tid & 31;
    const size_t base = (size_t)bt * CDIM;

    float4 z;
    if (a32) {
        z = ((const float4*)(a32 + base))[tid];
    } else {
        const uint2 av = ((const uint2*)(a16 + base))[tid];
        const __half2* pa = (const __half2*)&av;
        const float2 a01 = __half22float2(pa[0]);
        const float2 a23 = __half22float2(pa[1]);
        z = make_float4(a01.x, a01.y, a23.x, a23.y);
    }
    float hx, hy, hz, hw;
    if (hb16) {
        const uint2 hv = ((const uint2*)(hb16 + base))[tid];
        const __half2* ph = (const __half2*)&hv;
        const float2 h01 = __half22float2(ph[0]);
        const float2 h23 = __half22float2(ph[1]);
        hx = h01.x; hy = h01.y; hz = h23.x; hw = h23.y;
    } else {
        float4 pa = ((const float4*)(hb32a + base))[tid];
        float4 pb = ((const float4*)(hb32b + base))[tid];
        hx = pa.x + pb.x; hy = pa.y + pb.y; hz = pa.z + pb.z; hw = pa.w + pb.w;
    }
    if (relu_h) {
        hx = fmaxf(hx, 0.f); hy = fmaxf(hy, 0.f);
        hz = fmaxf(hz, 0.f); hw = fmaxf(hw, 0.f);
    }
    z.x += hx; z.y += hy; z.z += hz; z.w += hw;

    float s = z.x + z.y + z.z + z.w;
    float ss = z.x * z.x + z.y * z.y + z.z * z.z + z.w * z.w;
#pragma unroll
    for (int o = 16; o > 0; o >>= 1) {
        s += __shfl_xor_sync(0xffffffffu, s, o);
        ss += __shfl_xor_sync(0xffffffffu, ss, o);
    }
    if (lid == 0) { sh1[wid] = s; sh2[wid] = ss; }
    __syncthreads();
    float ts = 0.f, tss = 0.f;
#pragma unroll
    for (int j = 0; j < 8; j++) { ts += sh1[j]; tss += sh2[j]; }

    const float mean = ts * (1.f / CDIM);
    const float var = tss * (1.f / CDIM) - mean * mean;
    const float rstd = rsqrtf(var + 1e-5f);

    const float4 gg = ((const float4*)g)[tid];
    const float4 bb = ((const float4*)beta)[tid];
    float4 o4;
    o4.x = (z.x - mean) * rstd * gg.x + bb.x;
    o4.y = (z.y - mean) * rstd * gg.y + bb.y;
    o4.z = (z.z - mean) * rstd * gg.z + bb.z;
    o4.w = (z.w - mean) * rstd * gg.w + bb.w;
    if (out32)
        ((float4*)(out32 + base))[tid] = o4;
    if (out16) {
        const size_t b2 = (size_t)bt * (CDIM / 2) + tid * 2;
        ((__half2*)out16)[b2] =
            __halves2half2(__float2half_rn(o4.x), __float2half_rn(o4.y));
        ((__half2*)out16)[b2 + 1] =
            __halves2half2(__float2half_rn(o4.z), __float2half_rn(o4.w));
    }
}

// ---------------------------------------------------------------------------
// Launch
// ---------------------------------------------------------------------------
extern "C" void kernel_launch(void* const* d_in, const int* in_sizes, int n_in,
                              void* d_out, int out_size)
{
    const float* x    = (const float*)d_in[0];
    const float* radj = (const float*)d_in[1];
    const int*   inxs = (const int*)  d_in[2];
    const float* Wq   = (const float*)d_in[3];
    const float* Wk   = (const float*)d_in[4];
    const float* Wv   = (const float*)d_in[5];
    const float* Wo   = (const float*)d_in[6];
    const float* ln1g = (const float*)d_in[7];
    const float* ln1b = (const float*)d_in[8];
    const float* W1   = (const float*)d_in[9];
    const float* b1   = (const float*)d_in[10];
    const float* W2   = (const float*)d_in[11];
    const float* b2   = (const float*)d_in[12];
    const float* ln2g = (const float*)d_in[13];
    const float* ln2b = (const float*)d_in[14];
    float* out = (float*)d_out;

    __half *qkv, *h1, *yh, *xh, *hid, *wqkvh, *wvh, *woh, *w1h, *w2h;
    float *fpa, *fpb, *wp;
    cudaGetSymbolAddress((void**)&qkv, g_qkv);
    cudaGetSymbolAddress((void**)&h1, g_h1);
    cudaGetSymbolAddress((void**)&yh, g_yh);
    cudaGetSymbolAddress((void**)&xh, g_xh);
    cudaGetSymbolAddress((void**)&hid, g_hid);
    cudaGetSymbolAddress((void**)&fpa, g_fpa);
    cudaGetSymbolAddress((void**)&fpb, g_fpb);
    cudaGetSymbolAddress((void**)&wp, g_wp);
    cudaGetSymbolAddress((void**)&wqkvh, g_wqkvh);
    cudaGetSymbolAddress((void**)&wvh, g_wvh);
    cudaGetSymbolAddress((void**)&woh, g_woh);
    cudaGetSymbolAddress((void**)&w1h, g_w1h);
    cudaGetSymbolAddress((void**)&w2h, g_w2h);

    cudaFuncSetAttribute(mm_fp16_kernel,
                         cudaFuncAttributeMaxDynamicSharedMemorySize, MM_SMEM);
    cudaFuncSetAttribute(mm_prep_kernel,
                         cudaFuncAttributeMaxDynamicSharedMemorySize, MM_SMEM);
    cudaFuncSetAttribute(mm_f2_kernel,
                         cudaFuncAttributeMaxDynamicSharedMemorySize, MM_SMEM);

    const dim3 b256(256);

    // Prep: transposes (Wq,Wk,Wo,W1,W2), plain fp16 Wv, x -> fp16.
    thalf_all_kernel<<<dim3(HDIM / 32, HDIM / 32, 5), dim3(32, 8)>>>(
        Wq, Wk, Wo, W1, W2, wqkvh, woh, w1h, w2h);
    tohalf_kernel<<<(CDIM * CDIM / 4 + 255) / 256, b256>>>(Wv, wvh, CDIM * CDIM / 4);
    tohalf_kernel<<<(MDIM * CDIM / 4 + 255) / 256, b256>>>(x, xh, MDIM * CDIM / 4);
    // Wvo^T = Wo^T @ Wv^T(prod form), split-K x4 then reduce -> QKV stack block 3.
    mm_prep_kernel<<<dim3(CDIM / BN, CDIM / BM, 4), 256, MM_SMEM>>>(woh, wvh, wp);
    reduce4_kernel<<<CDIM * CDIM / 2 / 256, b256>>>(
        wp, wqkvh + (size_t)2 * CDIM * CDIM);

    const dim3 gQKV(QKVLD / BN, MDIM / BM);  // (12, 128)
    const dim3 gCH(HDIM / BN, MDIM / BM);    // (6, 128)

    const __half* a16 = xh;
    for (int hop = 0; hop < 2; hop++) {
        // q|k|vo = a @ [Wq | Wk | Wvo]^T
        mm_fp16_kernel<<<gQKV, 256, MM_SMEM>>>(a16, wqkvh, nullptr, qkv,
                                               nullptr, QKVLD, CDIM, 2);
        attn_kernel<<<MDIM, b256>>>(qkv, radj, inxs, h1);
        a16 = h1;
    }

    // y = LN(x + relu(h))  -> fp16 only
    ln_kernel<<<MDIM, b256>>>(x, nullptr, h1, nullptr, nullptr,
                              ln1g, ln1b, nullptr, yh, 1);
    // hid = relu(y @ W1 + b1)  -> fp16
    mm_fp16_kernel<<<gCH, 256, MM_SMEM>>>(yh, w1h, nullptr, hid, b1, HDIM, CDIM, 1 | 2);
    // f = hid @ W2 + b2  -> split-K x2 fp32 partials (bias in partial 0)
    mm_f2_kernel<<<dim3(CDIM / BN, MDIM / BM, 2), 256, MM_SMEM>>>(
        hid, w2h, fpa, fpb, b2);
    // out = LN(y + (fpa + fpb))  -> fp32 (d_out)
    ln_kernel<<<MDIM, b256>>>(nullptr, yh, nullptr, fpa, fpb,
                              ln2g, ln2b, out, nullptr, 0);
}

// round 17
// speedup vs baseline: 1.7079x; 1.2480x over previous
#include <cuda_runtime.h>
#include <cuda_fp16.h>
#include <cstdint>
#include <math.h>

// ============================================================================
// ReasonNet via ldmatrix + mma.sync (HMMA), pure fp16 GEMMs (fp32 accum).
// Round 17: BOTH weight folds, race-free:
//   Wg  = Wq@Wk^T : score_j = (h@Wg) . h[row_j]
//   Wvo = Wv@Wo   : h_next  = sum_j w_j * (h@Wvo)[row_j]
// Hop-2 attention writes h2 (NEVER aliases its gather source h1 — the round-15
// bug).  Per-hop N: 3072 -> 2048; GEMM units 9 -> 7.
// Prep: both C^3 products split-K x4 in ONE 256-CTA launch + batched reduce.
// FFN2 split-K x2 with fp32 partials summed in ln2 (round-16, verified).
// B=16, T=1024, C=1024, K=8, H=1536.  M = B*T = 16384.
// ============================================================================

#define MDIM 16384
#define CDIM 1024
#define HDIM 1536
#define KNEI 8
#define TSEQ 1024
#define GVLD 2048

#define BK 32
#define KSTRIDE 40                  // halfs per smem row (80B: aligned + LDSM conflict-free)
#define ROWB 80
#define BM 128
#define BN 256
#define STG_A 0
#define STG_B 10240                 // 128*80
#define STG_BYTES 30720             // + 256*80
#define NSTG 4
#define MM_SMEM (NSTG * STG_BYTES)  // 122880 bytes (1 CTA/SM)

// ---------------------------------------------------------------------------
// Scratch (static device globals; runtime allocation forbidden).
// ---------------------------------------------------------------------------
__device__ __half g_gv  [(size_t)MDIM * GVLD];    // fused g|vo per hop (fp16)
__device__ __half g_h1  [(size_t)MDIM * CDIM];    // hop-1 attn output
__device__ __half g_h2  [(size_t)MDIM * CDIM];    // hop-2 attn output (distinct!)
__device__ __half g_yh  [(size_t)MDIM * CDIM];    // ln1 output (fp16)
__device__ __half g_xh  [(size_t)MDIM * CDIM];
__device__ __half g_hid [(size_t)MDIM * HDIM];
__device__ float  g_fpa [(size_t)MDIM * CDIM];    // FFN2 split-K partial 0 (fp32)
__device__ float  g_fpb [(size_t)MDIM * CDIM];    // FFN2 split-K partial 1 (fp32)
__device__ float  g_wp  [(size_t)8 * CDIM * CDIM];// weight-product partials (fp32)
// fp16 weights.  Per-hop B stack: rows 0-1023 Wg^T, 1024-2047 Wvo^T.
__device__ __half g_wgv[(size_t)GVLD * CDIM];
__device__ __half g_wqh[(size_t)CDIM * CDIM];     // Wq row-major fp16
__device__ __half g_wkh[(size_t)CDIM * CDIM];     // Wk row-major fp16
__device__ __half g_wvh[(size_t)CDIM * CDIM];     // Wv row-major fp16
__device__ __half g_woh[(size_t)CDIM * CDIM];     // Wo^T fp16
__device__ __half g_w1h[(size_t)HDIM * CDIM];
__device__ __half g_w2h[(size_t)CDIM * HDIM];

// ---------------------------------------------------------------------------
// PTX helpers (sm_80-portable only)
// ---------------------------------------------------------------------------
__device__ __forceinline__ uint32_t smem_u32(const void* p) {
    uint32_t a;
    asm("{ .reg .u64 t; cvta.to.shared.u64 t, %1; cvt.u32.u64 %0, t; }"
        : "=r"(a) : "l"(p));
    return a;
}
__device__ __forceinline__ void cp16(uint32_t s, const void* g) {
    asm volatile("cp.async.cg.shared.global [%0], [%1], 16;" :: "r"(s), "l"(g) : "memory");
}
__device__ __forceinline__ void ldsm4(uint32_t* r, uint32_t addr) {
    asm volatile("ldmatrix.sync.aligned.m8n8.x4.shared.b16 {%0,%1,%2,%3}, [%4];"
                 : "=r"(r[0]), "=r"(r[1]), "=r"(r[2]), "=r"(r[3]) : "r"(addr));
}
__device__ __forceinline__ void mma16816(float* c, const uint32_t* a, const uint32_t* b) {
    asm volatile(
        "mma.sync.aligned.m16n8k16.row.col.f32.f16.f16.f32 "
        "{%0,%1,%2,%3}, {%4,%5,%6,%7}, {%8,%9}, {%0,%1,%2,%3};"
        : "+f"(c[0]), "+f"(c[1]), "+f"(c[2]), "+f"(c[3])
        : "r"(a[0]), "r"(a[1]), "r"(a[2]), "r"(a[3]), "r"(b[0]), "r"(b[1]));
}
__device__ __forceinline__ float dot8(uint4 a, uint4 c) {
    const __half2* pa = (const __half2*)&a;
    const __half2* pc = (const __half2*)&c;
    float s = 0.f;
#pragma unroll
    for (int i = 0; i < 4; i++) {
        float2 fa = __half22float2(pa[i]);
        float2 fc = __half22float2(pc[i]);
        s += fa.x * fc.x + fa.y * fc.y;
    }
    return s;
}

// ---------------------------------------------------------------------------
// GEMM device body: C[M,N] = A[M,0:K] @ B[N,0:K]^T, rows strided by lda.
// flags: bit0 relu, bit1 write fp16 (Ch), bit2 write fp32 (Cf).
// 256 threads, 128x256 CTA tile, 64x64 warp tile, BK=32, 4-stage pipeline.
// (Round-9 mainloop — verified best.)
// ---------------------------------------------------------------------------
__device__ __forceinline__ void mm_body(const __half* __restrict__ A,
                                        const __half* __restrict__ B,
                                        float* __restrict__ Cf, __half* __restrict__ Ch,
                                        const float* __restrict__ bias,
                                        int N, int K, int lda, int flags, char* smem)
{
    const uint32_t sb = smem_u32(smem);
    const int tid  = threadIdx.x;
    const int wid  = tid >> 5;
    const int lane = tid & 31;
    const int bm   = blockIdx.y * BM;
    const int bn   = blockIdx.x * BN;
    const int wm   = (wid >> 2) * 64;
    const int wn   = (wid & 3) * 64;
    const int ntiles = K / BK;

    const int rowA = tid & 127;
    const int sgA  = tid >> 7;
    const __half* gA = A + (size_t)(bm + rowA) * lda;
    const __half* gB = B + (size_t)(bn + tid) * lda;
    const uint32_t doffA = (uint32_t)rowA * ROWB;
    const uint32_t doffB = (uint32_t)tid * ROWB;

    auto issue = [&](int kt, int s) {
        const uint32_t st = sb + (uint32_t)s * STG_BYTES;
        const size_t kof = (size_t)kt * BK;
#pragma unroll
        for (int qq = 0; qq < 2; qq++) {
            const int seg = sgA + qq * 2;
            cp16(st + STG_A + doffA + seg * 16, gA + kof + seg * 8);
        }
#pragma unroll
        for (int seg = 0; seg < 4; seg++)
            cp16(st + STG_B + doffB + seg * 16, gB + kof + seg * 8);
        asm volatile("cp.async.commit_group;" ::: "memory");
    };

    float acc[4][8][4];
#pragma unroll
    for (int i = 0; i < 4; i++)
#pragma unroll
        for (int j = 0; j < 8; j++)
#pragma unroll
            for (int l = 0; l < 4; l++) acc[i][j][l] = 0.f;

    issue(0, 0);
    issue(1, 1);
    issue(2, 2);

    const int arow  = lane & 15;
    const int acol8 = (lane >> 4) * 8;
    const int brow  = (lane & 7) + ((lane >> 4) << 3);
    const int bcol8 = ((lane >> 3) & 1) * 8;

    for (int kt = 0; kt < ntiles; kt++) {
        if (kt < ntiles - 2)
            asm volatile("cp.async.wait_group 2;" ::: "memory");
        else if (kt == ntiles - 2)
            asm volatile("cp.async.wait_group 1;" ::: "memory");
        else
            asm volatile("cp.async.wait_group 0;" ::: "memory");
        __syncthreads();

        const uint32_t stg = sb + (uint32_t)(kt % NSTG) * STG_BYTES;
#pragma unroll
        for (int ks = 0; ks < 2; ks++) {
            const int kb = ks * 16;
            uint32_t af[4][4], bf[4][4];
#pragma unroll
            for (int mt = 0; mt < 4; mt++) {
                const uint32_t off =
                    (uint32_t)((wm + mt * 16 + arow) * KSTRIDE + kb + acol8) * 2;
                ldsm4(af[mt], stg + STG_A + off);
            }
#pragma unroll
            for (int nt2 = 0; nt2 < 4; nt2++) {
                const uint32_t off =
                    (uint32_t)((wn + nt2 * 16 + brow) * KSTRIDE + kb + bcol8) * 2;
                ldsm4(bf[nt2], stg + STG_B + off);
            }
#pragma unroll
            for (int mt = 0; mt < 4; mt++)
#pragma unroll
                for (int nt = 0; nt < 8; nt++)
                    mma16816(acc[mt][nt], af[mt], &bf[nt >> 1][(nt & 1) * 2]);
        }
        if (kt + 3 < ntiles) issue(kt + 3, (kt + 3) % NSTG);
    }

    const int g = lane >> 2;
    const int t = lane & 3;
#pragma unroll
    for (int mt = 0; mt < 4; mt++)
#pragma unroll
        for (int nt = 0; nt < 8; nt++) {
            const int gcol = bn + wn + nt * 8 + t * 2;
            float b0 = 0.f, b1 = 0.f;
            if (bias) { b0 = __ldg(&bias[gcol]); b1 = __ldg(&bias[gcol + 1]); }
#pragma unroll
            for (int half_ = 0; half_ < 2; half_++) {
                const int grow = bm + wm + mt * 16 + g + half_ * 8;
                float v0 = acc[mt][nt][half_ * 2 + 0] + b0;
                float v1 = acc[mt][nt][half_ * 2 + 1] + b1;
                if (flags & 1) { v0 = fmaxf(v0, 0.f); v1 = fmaxf(v1, 0.f); }
                const size_t o = (size_t)grow * N + gcol;
                if (flags & 4)
                    *(float2*)(Cf + o) = make_float2(v0, v1);
                if (flags & 2)
                    *(__half2*)(Ch + o) =
                        __halves2half2(__float2half_rn(v0), __float2half_rn(v1));
            }
        }
}

__global__ __launch_bounds__(256, 1)
void mm_fp16_kernel(const __half* __restrict__ A, const __half* __restrict__ B,
                    float* __restrict__ Cf, __half* __restrict__ Ch,
                    const float* __restrict__ bias, int N, int K, int flags)
{
    extern __shared__ char smem[];
    mm_body(A, B, Cf, Ch, bias, N, K, K, flags, smem);
}

// Both weight products, split-K x4 each, one launch (z = 0..7):
//   z in [0,4):  Wvo partial z:  sum_{j in z-range} Wo^T[m][j]*Wv[n][j]
//   z in [4,8):  Wg  partial:    sum_{j in range}  Wk[m][j]*Wq[n][j]
__global__ __launch_bounds__(256, 1)
void mm_prep8_kernel(const __half* __restrict__ woh, const __half* __restrict__ wvh,
                     const __half* __restrict__ wkh, const __half* __restrict__ wqh,
                     float* __restrict__ P)
{
    extern __shared__ char smem[];
    const int z = blockIdx.z;
    if (z < 4) {
        mm_body(woh + z * 256, wvh + z * 256, P + (size_t)z * CDIM * CDIM, nullptr,
                nullptr, CDIM, 256, CDIM, 4, smem);
    } else {
        const int zz = z - 4;
        mm_body(wkh + zz * 256, wqh + zz * 256, P + (size_t)z * CDIM * CDIM, nullptr,
                nullptr, CDIM, 256, CDIM, 4, smem);
    }
}

// Reduce partials -> fp16.  z=0: slots 0-3 -> Wvo block (wgv rows 1024+).
//                           z=1: slots 4-7 -> Wg  block (wgv rows 0-1023).
__global__ void reduce8_kernel(const float* __restrict__ P, __half* __restrict__ wgv)
{
    const size_t n = (size_t)CDIM * CDIM;
    const int z = blockIdx.z;
    const float* base = P + (size_t)(z == 0 ? 0 : 4) * n;
    __half* O = wgv + (z == 0 ? n : 0);
    size_t i = (size_t)(blockIdx.x * blockDim.x + threadIdx.x) * 2;
    float2 a = *(const float2*)(base + i);
    float2 b = *(const float2*)(base + n + i);
    float2 c = *(const float2*)(base + 2 * n + i);
    float2 d = *(const float2*)(base + 3 * n + i);
    *(__half2*)(O + i) = __halves2half2(__float2half_rn(a.x + b.x + c.x + d.x),
                                        __float2half_rn(a.y + b.y + c.y + d.y));
}

// FFN2 split-K x2: z=0 covers K [0,768) WITH bias, z=1 covers [768,1536).
__global__ __launch_bounds__(256, 1)
void mm_f2_kernel(const __half* __restrict__ A, const __half* __restrict__ B,
                  float* __restrict__ P0, float* __restrict__ P1,
                  const float* __restrict__ bias)
{
    extern __shared__ char smem[];
    const int z = blockIdx.z;
    const int koff = z * (HDIM / 2);
    mm_body(A + koff, B + koff, z == 0 ? P0 : P1, nullptr,
            z == 0 ? bias : nullptr, CDIM, HDIM / 2, HDIM, 4, smem);
}

// ---------------------------------------------------------------------------
// Weight transposes (Wo, W1, W2); z selects.
// ---------------------------------------------------------------------------
__global__ void thalf_all_kernel(const float* __restrict__ Wo,
                                 const float* __restrict__ W1, const float* __restrict__ W2,
                                 __half* __restrict__ wo,
                                 __half* __restrict__ w1, __half* __restrict__ w2)
{
    const float* W;
    __half* T;
    int Kd, Nd;
    switch (blockIdx.z) {
        case 0: W = Wo; T = wo; Kd = CDIM; Nd = CDIM; break;
        case 1: W = W1; T = w1; Kd = CDIM; Nd = HDIM; break;
        default: W = W2; T = w2; Kd = HDIM; Nd = CDIM; break;
    }
    const int bx = blockIdx.x * 32;
    const int by = blockIdx.y * 32;
    if (bx >= Nd || by >= Kd) return;

    __shared__ float t[32][33];
    const int x = threadIdx.x, y0 = threadIdx.y;
#pragma unroll
    for (int dy = 0; dy < 32; dy += 8)
        t[y0 + dy][x] = W[(size_t)(by + y0 + dy) * Nd + bx + x];
    __syncthreads();
#pragma unroll
    for (int dy = 0; dy < 32; dy += 8)
        T[(size_t)(bx + y0 + dy) * Kd + by + x] = __float2half_rn(t[x][y0 + dy]);
}

// Batched elementwise fp32 -> fp16 (no transpose); z selects among Wq, Wk, Wv.
__global__ void tohalf3_kernel(const float* __restrict__ i0, __half* __restrict__ o0,
                               const float* __restrict__ i1, __half* __restrict__ o1,
                               const float* __restrict__ i2, __half* __restrict__ o2)
{
    const float* in;
    __half* o;
    switch (blockIdx.z) {
        case 0: in = i0; o = o0; break;
        case 1: in = i1; o = o1; break;
        default: in = i2; o = o2; break;
    }
    int i = blockIdx.x * blockDim.x + threadIdx.x;
    float4 a = ((const float4*)in)[i];
    ((__half2*)o)[i * 2]     = __halves2half2(__float2half_rn(a.x), __float2half_rn(a.y));
    ((__half2*)o)[i * 2 + 1] = __halves2half2(__float2half_rn(a.z), __float2half_rn(a.w));
}

__global__ void tohalf_kernel(const float* __restrict__ in, __half* __restrict__ o,
                              int n4)
{
    int i = blockIdx.x * blockDim.x + threadIdx.x;
    if (i >= n4) return;
    float4 a = ((const float4*)in)[i];
    ((__half2*)o)[i * 2]     = __halves2half2(__float2half_rn(a.x), __float2half_rn(a.y));
    ((__half2*)o)[i * 2 + 1] = __halves2half2(__float2half_rn(a.z), __float2half_rn(a.w));
}

// ---------------------------------------------------------------------------
// Neighbor attention (K=8).  gv[M][2048] = g|vo;  act = hop-input activations.
//   score_j = g[bt] . act[row_j];  h_out[bt] = sum_j w_j * vo[row_j].
// hout MUST NOT alias act (gather race otherwise).
// ---------------------------------------------------------------------------
__global__ __launch_bounds__(256)
void attn_kernel(const __half* __restrict__ gv, const __half* __restrict__ act,
                 const float* __restrict__ radj, const int* __restrict__ inxs,
                 __half* __restrict__ hout)
{
    const int bt = blockIdx.x;
    const int b = bt >> 10;
    const int tid = threadIdx.x;
    const int wid = tid >> 5, lid = tid & 31;

    __shared__ float s_scores[KNEI];
    __shared__ int s_rows[KNEI];
    if (tid < KNEI) s_rows[tid] = b * TSEQ + inxs[(size_t)bt * KNEI + tid];
    __syncthreads();

    const uint4* qv = (const uint4*)(gv + (size_t)bt * GVLD);
    const uint4* kv = (const uint4*)(act + (size_t)s_rows[wid] * CDIM);
    float sum = 0.f;
#pragma unroll
    for (int e = lid; e < CDIM / 8; e += 32)
        sum += dot8(qv[e], kv[e]);
#pragma unroll
    for (int o = 16; o > 0; o >>= 1) sum += __shfl_xor_sync(0xffffffffu, sum, o);
    if (lid == 0)
        s_scores[wid] = sum * 0.03125f + radj[(size_t)bt * KNEI + wid];
    __syncthreads();

    float w[KNEI];
    float mx = s_scores[0];
#pragma unroll
    for (int j = 1; j < KNEI; j++) mx = fmaxf(mx, s_scores[j]);
    float den = 0.f;
#pragma unroll
    for (int j = 0; j < KNEI; j++) { w[j] = expf(s_scores[j] - mx); den += w[j]; }
    const float inv = 1.f / den;

    float a0 = 0.f, a1 = 0.f, a2 = 0.f, a3 = 0.f;
#pragma unroll
    for (int j = 0; j < KNEI; j++) {
        const uint2 vv =
            ((const uint2*)(gv + (size_t)s_rows[j] * GVLD + CDIM))[tid];
        const __half2* pv = (const __half2*)&vv;
        const float2 f0 = __half22float2(pv[0]);
        const float2 f1 = __half22float2(pv[1]);
        const float wj = w[j] * inv;
        a0 = fmaf(wj, f0.x, a0); a1 = fmaf(wj, f0.y, a1);
        a2 = fmaf(wj, f1.x, a2); a3 = fmaf(wj, f1.y, a3);
    }
    uint2 ov;
    ((__half2*)&ov)[0] = __halves2half2(__float2half_rn(a0), __float2half_rn(a1));
    ((__half2*)&ov)[1] = __halves2half2(__float2half_rn(a2), __float2half_rn(a3));
    ((uint2*)(hout + (size_t)bt * CDIM))[tid] = ov;
}

// ---------------------------------------------------------------------------
// Fused residual (+optional relu) LayerNorm.
// Base: a32 (fp32) or a16 (fp16).  Branch: hb16, OR hb32a+hb32b (fp32 partials).
// ---------------------------------------------------------------------------
__global__ __launch_bounds__(256)
void ln_kernel(const float* __restrict__ a32, const __half* __restrict__ a16,
               const __half* __restrict__ hb16,
               const float* __restrict__ hb32a, const float* __restrict__ hb32b,
               const float* __restrict__ g, const float* __restrict__ beta,
               float* __restrict__ out32, __half* __restrict__ out16, int relu_h)
{
    __shared__ float sh1[8], sh2[8];
    const int bt = blockIdx.x;
    const int tid = threadIdx.x;
    const int wid = tid >> 5, lid = tid & 31;
    const size_t base = (size_t)bt * CDIM;

    float4 z;
    if (a32) {
        z = ((const float4*)(a32 + base))[tid];
    } else {
        const uint2 av = ((const uint2*)(a16 + base))[tid];
        const __half2* pa = (const __half2*)&av;
        const float2 a01 = __half22float2(pa[0]);
        const float2 a23 = __half22float2(pa[1]);
        z = make_float4(a01.x, a01.y, a23.x, a23.y);
    }
    float hx, hy, hz, hw;
    if (hb16) {
        const uint2 hv = ((const uint2*)(hb16 + base))[tid];
        const __half2* ph = (const __half2*)&hv;
        const float2 h01 = __half22float2(ph[0]);
        const float2 h23 = __half22float2(ph[1]);
        hx = h01.x; hy = h01.y; hz = h23.x; hw = h23.y;
    } else {
        float4 pa = ((const float4*)(hb32a + base))[tid];
        float4 pb = ((const float4*)(hb32b + base))[tid];
        hx = pa.x + pb.x; hy = pa.y + pb.y; hz = pa.z + pb.z; hw = pa.w + pb.w;
    }
    if (relu_h) {
        hx = fmaxf(hx, 0.f); hy = fmaxf(hy, 0.f);
        hz = fmaxf(hz, 0.f); hw = fmaxf(hw, 0.f);
    }
    z.x += hx; z.y += hy; z.z += hz; z.w += hw;

    float s = z.x + z.y + z.z + z.w;
    float ss = z.x * z.x + z.y * z.y + z.z * z.z + z.w * z.w;
#pragma unroll
    for (int o = 16; o > 0; o >>= 1) {
        s += __shfl_xor_sync(0xffffffffu, s, o);
        ss += __shfl_xor_sync(0xffffffffu, ss, o);
    }
    if (lid == 0) { sh1[wid] = s; sh2[wid] = ss; }
    __syncthreads();
    float ts = 0.f, tss = 0.f;
#pragma unroll
    for (int j = 0; j < 8; j++) { ts += sh1[j]; tss += sh2[j]; }

    const float mean = ts * (1.f / CDIM);
    const float var = tss * (1.f / CDIM) - mean * mean;
    const float rstd = rsqrtf(var + 1e-5f);

    const float4 gg = ((const float4*)g)[tid];
    const float4 bb = ((const float4*)beta)[tid];
    float4 o4;
    o4.x = (z.x - mean) * rstd * gg.x + bb.x;
    o4.y = (z.y - mean) * rstd * gg.y + bb.y;
    o4.z = (z.z - mean) * rstd * gg.z + bb.z;
    o4.w = (z.w - mean) * rstd * gg.w + bb.w;
    if (out32)
        ((float4*)(out32 + base))[tid] = o4;
    if (out16) {
        const size_t b2 = (size_t)bt * (CDIM / 2) + tid * 2;
        ((__half2*)out16)[b2] =
            __halves2half2(__float2half_rn(o4.x), __float2half_rn(o4.y));
        ((__half2*)out16)[b2 + 1] =
            __halves2half2(__float2half_rn(o4.z), __float2half_rn(o4.w));
    }
}

// ---------------------------------------------------------------------------
// Launch
// ---------------------------------------------------------------------------
extern "C" void kernel_launch(void* const* d_in, const int* in_sizes, int n_in,
                              void* d_out, int out_size)
{
    const float* x    = (const float*)d_in[0];
    const float* radj = (const float*)d_in[1];
    const int*   inxs = (const int*)  d_in[2];
    const float* Wq   = (const float*)d_in[3];
    const float* Wk   = (const float*)d_in[4];
    const float* Wv   = (const float*)d_in[5];
    const float* Wo   = (const float*)d_in[6];
    const float* ln1g = (const float*)d_in[7];
    const float* ln1b = (const float*)d_in[8];
    const float* W1   = (const float*)d_in[9];
    const float* b1   = (const float*)d_in[10];
    const float* W2   = (const float*)d_in[11];
    const float* b2   = (const float*)d_in[12];
    const float* ln2g = (const float*)d_in[13];
    const float* ln2b = (const float*)d_in[14];
    float* out = (float*)d_out;

    __half *gv, *h1, *h2, *yh, *xh, *hid;
    __half *wgv, *wqh, *wkh, *wvh, *woh, *w1h, *w2h;
    float *fpa, *fpb, *wp;
    cudaGetSymbolAddress((void**)&gv, g_gv);
    cudaGetSymbolAddress((void**)&h1, g_h1);
    cudaGetSymbolAddress((void**)&h2, g_h2);
    cudaGetSymbolAddress((void**)&yh, g_yh);
    cudaGetSymbolAddress((void**)&xh, g_xh);
    cudaGetSymbolAddress((void**)&hid, g_hid);
    cudaGetSymbolAddress((void**)&fpa, g_fpa);
    cudaGetSymbolAddress((void**)&fpb, g_fpb);
    cudaGetSymbolAddress((void**)&wp, g_wp);
    cudaGetSymbolAddress((void**)&wgv, g_wgv);
    cudaGetSymbolAddress((void**)&wqh, g_wqh);
    cudaGetSymbolAddress((void**)&wkh, g_wkh);
    cudaGetSymbolAddress((void**)&wvh, g_wvh);
    cudaGetSymbolAddress((void**)&woh, g_woh);
    cudaGetSymbolAddress((void**)&w1h, g_w1h);
    cudaGetSymbolAddress((void**)&w2h, g_w2h);

    cudaFuncSetAttribute(mm_fp16_kernel,
                         cudaFuncAttributeMaxDynamicSharedMemorySize, MM_SMEM);
    cudaFuncSetAttribute(mm_prep8_kernel,
                         cudaFuncAttributeMaxDynamicSharedMemorySize, MM_SMEM);
    cudaFuncSetAttribute(mm_f2_kernel,
                         cudaFuncAttributeMaxDynamicSharedMemorySize, MM_SMEM);

    const dim3 b256(256);

    // Prep: transposes (Wo,W1,W2), plain fp16 (Wq,Wk,Wv), x -> fp16.
    thalf_all_kernel<<<dim3(HDIM / 32, HDIM / 32, 3), dim3(32, 8)>>>(
        Wo, W1, W2, woh, w1h, w2h);
    tohalf3_kernel<<<dim3(CDIM * CDIM / 4 / 256, 1, 3), b256>>>(
        Wq, wqh, Wk, wkh, Wv, wvh);
    tohalf_kernel<<<(MDIM * CDIM / 4 + 255) / 256, b256>>>(x, xh, MDIM * CDIM / 4);
    // Wvo (z 0-3) and Wg (z 4-7) products, split-K x4, one launch; then reduce.
    mm_prep8_kernel<<<dim3(CDIM / BN, CDIM / BM, 8), 256, MM_SMEM>>>(
        woh, wvh, wkh, wqh, wp);
    reduce8_kernel<<<dim3(CDIM * CDIM / 2 / 256, 1, 2), b256>>>(wp, wgv);

    const dim3 gGV(GVLD / BN, MDIM / BM);    // (8, 128)
    const dim3 gCH(HDIM / BN, MDIM / BM);    // (6, 128)

    // hop 1: gv = x @ [Wg | Wvo]^T;  attn gathers from xh, writes h1.
    mm_fp16_kernel<<<gGV, 256, MM_SMEM>>>(xh, wgv, nullptr, gv, nullptr,
                                          GVLD, CDIM, 2);
    attn_kernel<<<MDIM, b256>>>(gv, xh, radj, inxs, h1);
    // hop 2: gv = h1 @ [...]; attn gathers from h1, writes h2 (NO alias).
    mm_fp16_kernel<<<gGV, 256, MM_SMEM>>>(h1, wgv, nullptr, gv, nullptr,
                                          GVLD, CDIM, 2);
    attn_kernel<<<MDIM, b256>>>(gv, h1, radj, inxs, h2);

    // y = LN(x + relu(h2))  -> fp16 only
    ln_kernel<<<MDIM, b256>>>(x, nullptr, h2, nullptr, nullptr,
                              ln1g, ln1b, nullptr, yh, 1);
    // hid = relu(y @ W1 + b1)  -> fp16
    mm_fp16_kernel<<<gCH, 256, MM_SMEM>>>(yh, w1h, nullptr, hid, b1, HDIM, CDIM, 1 | 2);
    // f = hid @ W2 + b2  -> split-K x2 fp32 partials (bias in partial 0)
    mm_f2_kernel<<<dim3(CDIM / BN, MDIM / BM, 2), 256, MM_SMEM>>>(
        hid, w2h, fpa, fpb, b2);
    // out = LN(y + (fpa + fpb))  -> fp32 (d_out)
    ln_kernel<<<MDIM, b256>>>(nullptr, yh, nullptr, fpa, fpb,
                              ln2g, ln2b, out, nullptr, 0);
}